// round 4
// baseline (speedup 1.0000x reference)
#include <cuda_runtime.h>
#include <cstdint>

#define BN_EPS 1e-5f
#define MAXN 100000
#define MAXE 400000
#define MAXT 1000000

// ---- scratch (allocation-free, static device globals) ----
__device__ float g_Vsrc[(size_t)MAXN * 256];   // [N,256] = [core_src | gate_src]
__device__ float g_Vdst[(size_t)MAXN * 256];   // [N,256] = [core_dst | gate_dst]
__device__ float g_Ep  [(size_t)MAXE * 256];   // [E,256] = [core_bond | gate_bond]
__device__ float g_A   [(size_t)MAXT * 256];   // [T,256] fused core|gate (pre-BN)
__device__ float g_seg [(size_t)MAXE * 128];   // segment sums
__device__ float g_stats[512];                 // sumC | ssqC | sumG | ssqG
__device__ float g_scale[512];                 // aC | bC | aG | bG
__device__ float g_Wvs[256 * 128];             // [w_core_src ; w_gate_src]
__device__ float g_Wvd[256 * 128];             // [w_core_dst ; w_gate_dst]
__device__ float g_Web[256 * 128];             // [w_core_bond ; w_gate_bond]
__device__ float g_Wan[256 * 64];              // [w_core_angle ; w_gate_angle]

// ------------------------------------------------------------------
__global__ void zero_kernel(int E) {
    size_t n4 = (size_t)E * 32;
    size_t i = (size_t)blockIdx.x * blockDim.x + threadIdx.x;
    size_t st = (size_t)gridDim.x * blockDim.x;
    float4 z = make_float4(0.f, 0.f, 0.f, 0.f);
    float4* p = reinterpret_cast<float4*>(g_seg);
    for (size_t k = i; k < n4; k += st) p[k] = z;
    if (i < 512) g_stats[i] = 0.f;
}

// pack [a;b] -> out [256,K]
__global__ void pack_weights(const float* __restrict__ a, const float* __restrict__ b,
                             float* __restrict__ out, int elems) {
    int i = blockIdx.x * blockDim.x + threadIdx.x;
    if (i < elems) { out[i] = a[i]; out[elems + i] = b[i]; }
}

__device__ __forceinline__ uint32_t to_tf32(float x) {
    uint32_t r;
    asm("cvt.rna.tf32.f32 %0, %1;" : "=r"(r) : "f"(x));
    return r;
}

// ------------------------------------------------------------------
// tf32 mma.sync GEMM: C[bx*128 + m, by*128 + n] = X @ W^T (+ Dadd)
// ------------------------------------------------------------------
template<int K>
__global__ __launch_bounds__(256, 2)
void mma_gemm(const float* __restrict__ X, const float* __restrict__ W,
              const float* __restrict__ Dadd, float* __restrict__ C,
              int M, int ldc) {
    constexpr int BK = 64;
    constexpr int KP = BK + 4;
    extern __shared__ float smem[];
    float* Xs = smem;
    float* Ws = smem + 128 * KP;

    const int tid = threadIdx.x;
    const int lane = tid & 31;
    const int wid = tid >> 5;
    const int warpM = wid >> 2;
    const int warpN = wid & 3;
    const int g = lane >> 2;
    const int qc = lane & 3;
    const int row0 = blockIdx.x * 128;
    const int nBase = blockIdx.y * 128;

    float c[4][4][4];
#pragma unroll
    for (int mf = 0; mf < 4; ++mf)
#pragma unroll
        for (int nf = 0; nf < 4; ++nf)
#pragma unroll
            for (int q = 0; q < 4; ++q) c[mf][nf][q] = 0.f;

    for (int kt = 0; kt < K; kt += BK) {
        for (int i = tid; i < 128 * (BK / 4); i += 256) {
            int r = i >> 4;
            int k4 = (i & 15) << 2;
            int gr = row0 + r;
            float4 v = make_float4(0.f, 0.f, 0.f, 0.f);
            if (gr < M) v = *reinterpret_cast<const float4*>(X + (size_t)gr * K + kt + k4);
            uint32_t* dst = reinterpret_cast<uint32_t*>(Xs + r * KP + k4);
            dst[0] = to_tf32(v.x); dst[1] = to_tf32(v.y);
            dst[2] = to_tf32(v.z); dst[3] = to_tf32(v.w);
        }
        for (int i = tid; i < 128 * (BK / 4); i += 256) {
            int r = i >> 4;
            int k4 = (i & 15) << 2;
            float4 v = *reinterpret_cast<const float4*>(W + (size_t)(nBase + r) * K + kt + k4);
            uint32_t* dst = reinterpret_cast<uint32_t*>(Ws + r * KP + k4);
            dst[0] = to_tf32(v.x); dst[1] = to_tf32(v.y);
            dst[2] = to_tf32(v.z); dst[3] = to_tf32(v.w);
        }
        __syncthreads();

        const uint32_t* Xu = reinterpret_cast<const uint32_t*>(Xs);
        const uint32_t* Wu = reinterpret_cast<const uint32_t*>(Ws);
#pragma unroll
        for (int k0 = 0; k0 < BK; k0 += 8) {
            uint32_t a[4][4], b[4][2];
#pragma unroll
            for (int mf = 0; mf < 4; ++mf) {
                int r = warpM * 64 + mf * 16 + g;
                a[mf][0] = Xu[r * KP + k0 + qc];
                a[mf][1] = Xu[(r + 8) * KP + k0 + qc];
                a[mf][2] = Xu[r * KP + k0 + qc + 4];
                a[mf][3] = Xu[(r + 8) * KP + k0 + qc + 4];
            }
#pragma unroll
            for (int nf = 0; nf < 4; ++nf) {
                int n = warpN * 32 + nf * 8 + g;
                b[nf][0] = Wu[n * KP + k0 + qc];
                b[nf][1] = Wu[n * KP + k0 + qc + 4];
            }
#pragma unroll
            for (int mf = 0; mf < 4; ++mf)
#pragma unroll
                for (int nf = 0; nf < 4; ++nf) {
                    asm volatile(
                        "mma.sync.aligned.m16n8k8.row.col.f32.tf32.tf32.f32 "
                        "{%0,%1,%2,%3}, {%4,%5,%6,%7}, {%8,%9}, {%0,%1,%2,%3};"
                        : "+f"(c[mf][nf][0]), "+f"(c[mf][nf][1]),
                          "+f"(c[mf][nf][2]), "+f"(c[mf][nf][3])
                        : "r"(a[mf][0]), "r"(a[mf][1]), "r"(a[mf][2]), "r"(a[mf][3]),
                          "r"(b[nf][0]), "r"(b[nf][1]));
                }
        }
        __syncthreads();
    }

#pragma unroll
    for (int mf = 0; mf < 4; ++mf) {
        int r0 = row0 + warpM * 64 + mf * 16 + g;
        int r1 = r0 + 8;
#pragma unroll
        for (int nf = 0; nf < 4; ++nf) {
            int col = nBase + warpN * 32 + nf * 8 + qc * 2;
            if (r0 < M) {
                float2 o = make_float2(c[mf][nf][0], c[mf][nf][1]);
                if (Dadd) {
                    float2 d = *reinterpret_cast<const float2*>(Dadd + (size_t)r0 * ldc + col);
                    o.x += d.x; o.y += d.y;
                }
                *reinterpret_cast<float2*>(C + (size_t)r0 * ldc + col) = o;
            }
            if (r1 < M) {
                float2 o = make_float2(c[mf][nf][2], c[mf][nf][3]);
                if (Dadd) {
                    float2 d = *reinterpret_cast<const float2*>(Dadd + (size_t)r1 * ldc + col);
                    o.x += d.x; o.y += d.y;
                }
                *reinterpret_cast<float2*>(C + (size_t)r1 * ldc + col) = o;
            }
        }
    }
}

// ------------------------------------------------------------------
// Fused angle GEMM (K=64) + gather-add + BN stats.
// grid (ceil(T/128), 2): y=0 -> core half (cols 0-127), y=1 -> gate half.
// Epilogue: out[t, y*128+col] = angles + Vsrc[j] + Ep[k] + Vdst[i];
// per-column sum/sumsq accumulated via regs -> smem -> global atomics.
// ------------------------------------------------------------------
__global__ __launch_bounds__(256, 2)
void angle_gemm_fuse(const float* __restrict__ X, const float* __restrict__ W,
                     const int* __restrict__ kx, const int* __restrict__ jx,
                     const int* __restrict__ ix, int T) {
    constexpr int K = 64;
    constexpr int KP = K + 4;
    extern __shared__ float smem[];
    float* Xs = smem;
    float* Ws = smem + 128 * KP;
    __shared__ float s_sum[128];
    __shared__ float s_ssq[128];

    const int tid = threadIdx.x;
    const int lane = tid & 31;
    const int wid = tid >> 5;
    const int warpM = wid >> 2;
    const int warpN = wid & 3;
    const int g = lane >> 2;
    const int qc = lane & 3;
    const int row0 = blockIdx.x * 128;
    const int y = blockIdx.y;            // 0=core, 1=gate
    const int nBase = y * 128;

    if (tid < 128) { s_sum[tid] = 0.f; s_ssq[tid] = 0.f; }

    float c[4][4][4];
#pragma unroll
    for (int mf = 0; mf < 4; ++mf)
#pragma unroll
        for (int nf = 0; nf < 4; ++nf)
#pragma unroll
            for (int q = 0; q < 4; ++q) c[mf][nf][q] = 0.f;

    // single K-tile (K == BK == 64)
    for (int i = tid; i < 128 * (K / 4); i += 256) {
        int r = i >> 4;
        int k4 = (i & 15) << 2;
        int gr = row0 + r;
        float4 v = make_float4(0.f, 0.f, 0.f, 0.f);
        if (gr < T) v = *reinterpret_cast<const float4*>(X + (size_t)gr * K + k4);
        uint32_t* dst = reinterpret_cast<uint32_t*>(Xs + r * KP + k4);
        dst[0] = to_tf32(v.x); dst[1] = to_tf32(v.y);
        dst[2] = to_tf32(v.z); dst[3] = to_tf32(v.w);
    }
    for (int i = tid; i < 128 * (K / 4); i += 256) {
        int r = i >> 4;
        int k4 = (i & 15) << 2;
        float4 v = *reinterpret_cast<const float4*>(W + (size_t)(nBase + r) * K + k4);
        uint32_t* dst = reinterpret_cast<uint32_t*>(Ws + r * KP + k4);
        dst[0] = to_tf32(v.x); dst[1] = to_tf32(v.y);
        dst[2] = to_tf32(v.z); dst[3] = to_tf32(v.w);
    }
    __syncthreads();

    {
        const uint32_t* Xu = reinterpret_cast<const uint32_t*>(Xs);
        const uint32_t* Wu = reinterpret_cast<const uint32_t*>(Ws);
#pragma unroll
        for (int k0 = 0; k0 < K; k0 += 8) {
            uint32_t a[4][4], b[4][2];
#pragma unroll
            for (int mf = 0; mf < 4; ++mf) {
                int r = warpM * 64 + mf * 16 + g;
                a[mf][0] = Xu[r * KP + k0 + qc];
                a[mf][1] = Xu[(r + 8) * KP + k0 + qc];
                a[mf][2] = Xu[r * KP + k0 + qc + 4];
                a[mf][3] = Xu[(r + 8) * KP + k0 + qc + 4];
            }
#pragma unroll
            for (int nf = 0; nf < 4; ++nf) {
                int n = warpN * 32 + nf * 8 + g;
                b[nf][0] = Wu[n * KP + k0 + qc];
                b[nf][1] = Wu[n * KP + k0 + qc + 4];
            }
#pragma unroll
            for (int mf = 0; mf < 4; ++mf)
#pragma unroll
                for (int nf = 0; nf < 4; ++nf) {
                    asm volatile(
                        "mma.sync.aligned.m16n8k8.row.col.f32.tf32.tf32.f32 "
                        "{%0,%1,%2,%3}, {%4,%5,%6,%7}, {%8,%9}, {%0,%1,%2,%3};"
                        : "+f"(c[mf][nf][0]), "+f"(c[mf][nf][1]),
                          "+f"(c[mf][nf][2]), "+f"(c[mf][nf][3])
                        : "r"(a[mf][0]), "r"(a[mf][1]), "r"(a[mf][2]), "r"(a[mf][3]),
                          "r"(b[nf][0]), "r"(b[nf][1]));
                }
        }
    }
    __syncthreads();

    // ---- fused epilogue ----
    float sumv[8], ssqv[8];
#pragma unroll
    for (int e = 0; e < 8; ++e) { sumv[e] = 0.f; ssqv[e] = 0.f; }

#pragma unroll
    for (int mf = 0; mf < 4; ++mf) {
#pragma unroll
        for (int half = 0; half < 2; ++half) {
            int t = row0 + warpM * 64 + mf * 16 + g + half * 8;
            if (t < T) {
                int j = jx[t], k = kx[t], i2 = ix[t];
                const float* vs = g_Vsrc + (size_t)j  * 256 + nBase;
                const float* ep = g_Ep   + (size_t)k  * 256 + nBase;
                const float* vd = g_Vdst + (size_t)i2 * 256 + nBase;
                float* out = g_A + (size_t)t * 256 + nBase;
#pragma unroll
                for (int nf = 0; nf < 4; ++nf) {
                    int col = warpN * 32 + nf * 8 + qc * 2;
                    float2 a1 = *reinterpret_cast<const float2*>(vs + col);
                    float2 a2 = *reinterpret_cast<const float2*>(ep + col);
                    float2 a3 = *reinterpret_cast<const float2*>(vd + col);
                    float ox = c[mf][nf][half * 2 + 0] + a1.x + a2.x + a3.x;
                    float oy = c[mf][nf][half * 2 + 1] + a1.y + a2.y + a3.y;
                    *reinterpret_cast<float2*>(out + col) = make_float2(ox, oy);
                    sumv[nf * 2 + 0] += ox;
                    sumv[nf * 2 + 1] += oy;
                    ssqv[nf * 2 + 0] += ox * ox;
                    ssqv[nf * 2 + 1] += oy * oy;
                }
            }
        }
    }

    // reduce stats: regs -> smem -> global
#pragma unroll
    for (int nf = 0; nf < 4; ++nf) {
        int col = warpN * 32 + nf * 8 + qc * 2;
        atomicAdd(&s_sum[col + 0], sumv[nf * 2 + 0]);
        atomicAdd(&s_sum[col + 1], sumv[nf * 2 + 1]);
        atomicAdd(&s_ssq[col + 0], ssqv[nf * 2 + 0]);
        atomicAdd(&s_ssq[col + 1], ssqv[nf * 2 + 1]);
    }
    __syncthreads();
    if (tid < 128) {
        atomicAdd(&g_stats[y * 256 + tid], s_sum[tid]);
        atomicAdd(&g_stats[y * 256 + 128 + tid], s_ssq[tid]);
    }
}

// ------------------------------------------------------------------
__global__ void finalize_stats(const float* __restrict__ gamC, const float* __restrict__ betC,
                               const float* __restrict__ gamG, const float* __restrict__ betG,
                               float invT) {
    int c = threadIdx.x;  // 128 threads
    float m = g_stats[c] * invT;
    float v = g_stats[128 + c] * invT - m * m;
    float a = rsqrtf(v + BN_EPS) * gamC[c];
    g_scale[c] = a;
    g_scale[128 + c] = betC[c] - m * a;

    m = g_stats[256 + c] * invT;
    v = g_stats[384 + c] * invT - m * m;
    a = rsqrtf(v + BN_EPS) * gamG[c];
    g_scale[256 + c] = a;
    g_scale[384 + c] = betG[c] - m * a;
}

// ------------------------------------------------------------------
__device__ __forceinline__ float sigf(float x) { return 1.0f / (1.0f + __expf(-x)); }

__global__ void pass_scatter(const int* __restrict__ kx, int T) {
    const int lane = threadIdx.x & 31;
    int warp = (blockIdx.x * blockDim.x + threadIdx.x) >> 5;
    const int nw = (gridDim.x * blockDim.x) >> 5;

    const float4 ac = reinterpret_cast<const float4*>(g_scale)[lane];
    const float4 bc = reinterpret_cast<const float4*>(g_scale + 128)[lane];
    const float4 ag = reinterpret_cast<const float4*>(g_scale + 256)[lane];
    const float4 bg = reinterpret_cast<const float4*>(g_scale + 384)[lane];

    for (int t = warp; t < T; t += nw) {
        int k = kx[t];
        const float4* A = reinterpret_cast<const float4*>(g_A + (size_t)t * 256);
        float4 c = A[lane];
        float4 g = A[lane + 32];

        float cnx = c.x * ac.x + bc.x, cny = c.y * ac.y + bc.y;
        float cnz = c.z * ac.z + bc.z, cnw = c.w * ac.w + bc.w;
        float gnx = g.x * ag.x + bg.x, gny = g.y * ag.y + bg.y;
        float gnz = g.z * ag.z + bg.z, gnw = g.w * ag.w + bg.w;

        float ux = cnx * sigf(cnx) * sigf(gnx);
        float uy = cny * sigf(cny) * sigf(gny);
        float uz = cnz * sigf(cnz) * sigf(gnz);
        float uw = cnw * sigf(cnw) * sigf(gnw);

        float* dst = g_seg + (size_t)k * 128 + lane * 4;
        atomicAdd(dst + 0, ux);
        atomicAdd(dst + 1, uy);
        atomicAdd(dst + 2, uz);
        atomicAdd(dst + 3, uw);
    }
}

// ------------------------------------------------------------------
extern "C" void kernel_launch(void* const* d_in, const int* in_sizes, int n_in,
                              void* d_out, int out_size) {
    const float* vertex = (const float*)d_in[0];
    const float* edge   = (const float*)d_in[1];
    const float* angle  = (const float*)d_in[2];
    const int* kx = (const int*)d_in[4];
    const int* jx = (const int*)d_in[5];
    const int* ix = (const int*)d_in[6];
    const float* w_cs = (const float*)d_in[7];
    const float* w_cd = (const float*)d_in[8];
    const float* w_cb = (const float*)d_in[9];
    const float* w_ca = (const float*)d_in[10];
    const float* w_gs = (const float*)d_in[11];
    const float* w_gd = (const float*)d_in[12];
    const float* w_gb = (const float*)d_in[13];
    const float* w_ga = (const float*)d_in[14];
    const float* bcg = (const float*)d_in[15];
    const float* bcb = (const float*)d_in[16];
    const float* bgg = (const float*)d_in[17];
    const float* bgb = (const float*)d_in[18];
    const float* w_out = (const float*)d_in[19];

    const int N = in_sizes[0] / 128;
    const int E = in_sizes[1] / 128;
    const int T = in_sizes[2] / 64;

    float *pVsrc, *pVdst, *pEp, *pSeg, *pWvs, *pWvd, *pWeb, *pWan;
    cudaGetSymbolAddress((void**)&pVsrc, g_Vsrc);
    cudaGetSymbolAddress((void**)&pVdst, g_Vdst);
    cudaGetSymbolAddress((void**)&pEp, g_Ep);
    cudaGetSymbolAddress((void**)&pSeg, g_seg);
    cudaGetSymbolAddress((void**)&pWvs, g_Wvs);
    cudaGetSymbolAddress((void**)&pWvd, g_Wvd);
    cudaGetSymbolAddress((void**)&pWeb, g_Web);
    cudaGetSymbolAddress((void**)&pWan, g_Wan);

    const size_t smem_bytes = 2 * 128 * 68 * sizeof(float);  // 69632
    cudaFuncSetAttribute(mma_gemm<128>, cudaFuncAttributeMaxDynamicSharedMemorySize,
                         (int)smem_bytes);
    cudaFuncSetAttribute(angle_gemm_fuse, cudaFuncAttributeMaxDynamicSharedMemorySize,
                         (int)smem_bytes);

    zero_kernel<<<2048, 256>>>(E);
    pack_weights<<<64, 256>>>(w_cs, w_gs, pWvs, 16384);
    pack_weights<<<64, 256>>>(w_cd, w_gd, pWvd, 16384);
    pack_weights<<<64, 256>>>(w_cb, w_gb, pWeb, 16384);
    pack_weights<<<32, 256>>>(w_ca, w_ga, pWan, 8192);

    const int gN = (N + 127) / 128;
    const int gE = (E + 127) / 128;
    const int gT = (T + 127) / 128;

    // projections: core|gate packed -> N dimension 256 via gridDim.y = 2
    mma_gemm<128><<<dim3(gN, 2), 256, smem_bytes>>>(vertex, pWvs, nullptr, pVsrc, N, 256);
    mma_gemm<128><<<dim3(gN, 2), 256, smem_bytes>>>(vertex, pWvd, nullptr, pVdst, N, 256);
    mma_gemm<128><<<dim3(gE, 2), 256, smem_bytes>>>(edge,   pWeb, nullptr, pEp,   E, 256);

    // fused: angle GEMM + gather-add + BN stats (writes g_A once)
    angle_gemm_fuse<<<dim3(gT, 2), 256, smem_bytes>>>(angle, pWan, kx, jx, ix, T);

    finalize_stats<<<1, 128>>>(bcg, bcb, bgg, bgb, 1.0f / (float)T);

    // activation + segment scatter
    pass_scatter<<<1184, 256>>>(kx, T);

    // new_bond = seg @ w_out.T + edge_feat
    mma_gemm<128><<<dim3(gE, 1), 256, smem_bytes>>>(pSeg, w_out, edge, (float*)d_out, E, 128);
}

// round 5
// speedup vs baseline: 1.1719x; 1.1719x over previous
#include <cuda_runtime.h>
#include <cstdint>

#define BN_EPS 1e-5f
#define MAXN 100000
#define MAXE 400000
#define MAXT 1000000

// ---- scratch (allocation-free, static device globals) ----
__device__ float g_Vsrc[(size_t)MAXN * 256];   // [N,256] = [core_src | gate_src]
__device__ float g_Vdst[(size_t)MAXN * 256];   // [N,256] = [core_dst | gate_dst]
__device__ float g_Ep  [(size_t)MAXE * 256];   // [E,256] = [core_bond | gate_bond]
__device__ float g_A   [(size_t)MAXT * 256];   // [T,256] fused core|gate (pre-BN)
__device__ float g_seg [(size_t)MAXE * 128];   // segment sums
__device__ float g_stats[512];                 // sumC | ssqC | sumG | ssqG
__device__ float g_scale[512];                 // aC | bC | aG | bG
__device__ float g_Wv [512 * 128];             // [w_core_src; w_gate_src; w_core_dst; w_gate_dst]
__device__ float g_Web[256 * 128];             // [w_core_bond ; w_gate_bond]
__device__ float g_Wan[256 * 64];              // [w_core_angle ; w_gate_angle]

// ------------------------------------------------------------------
__global__ void zero_kernel(int E) {
    size_t n4 = (size_t)E * 32;
    size_t i = (size_t)blockIdx.x * blockDim.x + threadIdx.x;
    size_t st = (size_t)gridDim.x * blockDim.x;
    float4 z = make_float4(0.f, 0.f, 0.f, 0.f);
    float4* p = reinterpret_cast<float4*>(g_seg);
    for (size_t k = i; k < n4; k += st) p[k] = z;
    if (i < 512) g_stats[i] = 0.f;
}

// pack [a;b] -> out [2*elems]
__global__ void pack_weights(const float* __restrict__ a, const float* __restrict__ b,
                             float* __restrict__ out, int elems) {
    int i = blockIdx.x * blockDim.x + threadIdx.x;
    if (i < elems) { out[i] = a[i]; out[elems + i] = b[i]; }
}

__device__ __forceinline__ uint32_t to_tf32(float x) {
    uint32_t r;
    asm("cvt.rna.tf32.f32 %0, %1;" : "=r"(r) : "f"(x));
    return r;
}

// ------------------------------------------------------------------
// tf32 mma.sync GEMM core. Computes a 128x128 tile:
// out[m, colBase + n] = X[row0+m, :] . W[wBase + n, :]  (+ Dadd)
// ------------------------------------------------------------------
template<int K>
__device__ __forceinline__
void gemm_tile(const float* __restrict__ X, const float* __restrict__ W,
               const float* __restrict__ Dadd, float* __restrict__ C,
               int M, int ldc, int row0, int wBase, int colBase, float* smem) {
    constexpr int BK = 64;
    constexpr int KP = BK + 4;
    float* Xs = smem;
    float* Ws = smem + 128 * KP;

    const int tid = threadIdx.x;
    const int lane = tid & 31;
    const int wid = tid >> 5;
    const int warpM = wid >> 2;
    const int warpN = wid & 3;
    const int g = lane >> 2;
    const int qc = lane & 3;

    float c[4][4][4];
#pragma unroll
    for (int mf = 0; mf < 4; ++mf)
#pragma unroll
        for (int nf = 0; nf < 4; ++nf)
#pragma unroll
            for (int q = 0; q < 4; ++q) c[mf][nf][q] = 0.f;

    for (int kt = 0; kt < K; kt += BK) {
        for (int i = tid; i < 128 * (BK / 4); i += 256) {
            int r = i >> 4;
            int k4 = (i & 15) << 2;
            int gr = row0 + r;
            float4 v = make_float4(0.f, 0.f, 0.f, 0.f);
            if (gr < M) v = *reinterpret_cast<const float4*>(X + (size_t)gr * K + kt + k4);
            uint32_t* dst = reinterpret_cast<uint32_t*>(Xs + r * KP + k4);
            dst[0] = to_tf32(v.x); dst[1] = to_tf32(v.y);
            dst[2] = to_tf32(v.z); dst[3] = to_tf32(v.w);
        }
        for (int i = tid; i < 128 * (BK / 4); i += 256) {
            int r = i >> 4;
            int k4 = (i & 15) << 2;
            float4 v = *reinterpret_cast<const float4*>(W + (size_t)(wBase + r) * K + kt + k4);
            uint32_t* dst = reinterpret_cast<uint32_t*>(Ws + r * KP + k4);
            dst[0] = to_tf32(v.x); dst[1] = to_tf32(v.y);
            dst[2] = to_tf32(v.z); dst[3] = to_tf32(v.w);
        }
        __syncthreads();

        const uint32_t* Xu = reinterpret_cast<const uint32_t*>(Xs);
        const uint32_t* Wu = reinterpret_cast<const uint32_t*>(Ws);
#pragma unroll
        for (int k0 = 0; k0 < BK; k0 += 8) {
            uint32_t a[4][4], b[4][2];
#pragma unroll
            for (int mf = 0; mf < 4; ++mf) {
                int r = warpM * 64 + mf * 16 + g;
                a[mf][0] = Xu[r * KP + k0 + qc];
                a[mf][1] = Xu[(r + 8) * KP + k0 + qc];
                a[mf][2] = Xu[r * KP + k0 + qc + 4];
                a[mf][3] = Xu[(r + 8) * KP + k0 + qc + 4];
            }
#pragma unroll
            for (int nf = 0; nf < 4; ++nf) {
                int n = warpN * 32 + nf * 8 + g;
                b[nf][0] = Wu[n * KP + k0 + qc];
                b[nf][1] = Wu[n * KP + k0 + qc + 4];
            }
#pragma unroll
            for (int mf = 0; mf < 4; ++mf)
#pragma unroll
                for (int nf = 0; nf < 4; ++nf) {
                    asm volatile(
                        "mma.sync.aligned.m16n8k8.row.col.f32.tf32.tf32.f32 "
                        "{%0,%1,%2,%3}, {%4,%5,%6,%7}, {%8,%9}, {%0,%1,%2,%3};"
                        : "+f"(c[mf][nf][0]), "+f"(c[mf][nf][1]),
                          "+f"(c[mf][nf][2]), "+f"(c[mf][nf][3])
                        : "r"(a[mf][0]), "r"(a[mf][1]), "r"(a[mf][2]), "r"(a[mf][3]),
                          "r"(b[nf][0]), "r"(b[nf][1]));
                }
        }
        __syncthreads();
    }

#pragma unroll
    for (int mf = 0; mf < 4; ++mf) {
        int r0 = row0 + warpM * 64 + mf * 16 + g;
        int r1 = r0 + 8;
#pragma unroll
        for (int nf = 0; nf < 4; ++nf) {
            int col = colBase + warpN * 32 + nf * 8 + qc * 2;
            if (r0 < M) {
                float2 o = make_float2(c[mf][nf][0], c[mf][nf][1]);
                if (Dadd) {
                    float2 d = *reinterpret_cast<const float2*>(Dadd + (size_t)r0 * ldc + col);
                    o.x += d.x; o.y += d.y;
                }
                *reinterpret_cast<float2*>(C + (size_t)r0 * ldc + col) = o;
            }
            if (r1 < M) {
                float2 o = make_float2(c[mf][nf][2], c[mf][nf][3]);
                if (Dadd) {
                    float2 d = *reinterpret_cast<const float2*>(Dadd + (size_t)r1 * ldc + col);
                    o.x += d.x; o.y += d.y;
                }
                *reinterpret_cast<float2*>(C + (size_t)r1 * ldc + col) = o;
            }
        }
    }
}

template<int K>
__global__ __launch_bounds__(256, 2)
void mma_gemm(const float* __restrict__ X, const float* __restrict__ W,
              const float* __restrict__ Dadd, float* __restrict__ C,
              int M, int ldc) {
    extern __shared__ float smem[];
    gemm_tile<K>(X, W, Dadd, C, M, ldc, blockIdx.x * 128,
                 blockIdx.y * 128, blockIdx.y * 128, smem);
}

// merged vertex GEMM: y in 0..3 -> [Vsrc core, Vsrc gate, Vdst core, Vdst gate]
__global__ __launch_bounds__(256, 2)
void mma_gemm_vertex(const float* __restrict__ X, const float* __restrict__ W,
                     float* __restrict__ C0, float* __restrict__ C1, int M) {
    extern __shared__ float smem[];
    int y = blockIdx.y;
    float* C = (y < 2) ? C0 : C1;
    gemm_tile<128>(X, W, nullptr, C, M, 256, blockIdx.x * 128,
                   y * 128, (y & 1) * 128, smem);
}

// ------------------------------------------------------------------
// pass B: core/gate = A + Vsrc[j] + Ep[k] + Vdst[i] (in place), + BN stats.
// one warp per triplet, x2 unrolled for MLP; lane covers 4 cols per half.
// ------------------------------------------------------------------
__device__ __forceinline__ float4 f4add(float4 a, float4 b) {
    return make_float4(a.x + b.x, a.y + b.y, a.z + b.z, a.w + b.w);
}

__global__ void pass_fuse(const int* __restrict__ kx, const int* __restrict__ jx,
                          const int* __restrict__ ix, int T) {
    const int lane = threadIdx.x & 31;
    int warp = (blockIdx.x * blockDim.x + threadIdx.x) >> 5;
    const int nw = (gridDim.x * blockDim.x) >> 5;

    float4 sc = make_float4(0, 0, 0, 0), qc = make_float4(0, 0, 0, 0);
    float4 sg = make_float4(0, 0, 0, 0), qg = make_float4(0, 0, 0, 0);

    for (int t0 = warp * 2; t0 < T; t0 += nw * 2) {
        int t1 = t0 + 1;
        bool h1 = t1 < T;
        int j0 = jx[t0], k0 = kx[t0], i0 = ix[t0];
        int j1 = h1 ? jx[t1] : j0, k1 = h1 ? kx[t1] : k0, i1 = h1 ? ix[t1] : i0;

        float4* A0 = reinterpret_cast<float4*>(g_A + (size_t)t0 * 256);
        float4* A1 = reinterpret_cast<float4*>(g_A + (size_t)t1 * 256);
        const float4* Vs0 = reinterpret_cast<const float4*>(g_Vsrc + (size_t)j0 * 256);
        const float4* Ep0 = reinterpret_cast<const float4*>(g_Ep + (size_t)k0 * 256);
        const float4* Vd0 = reinterpret_cast<const float4*>(g_Vdst + (size_t)i0 * 256);
        const float4* Vs1 = reinterpret_cast<const float4*>(g_Vsrc + (size_t)j1 * 256);
        const float4* Ep1 = reinterpret_cast<const float4*>(g_Ep + (size_t)k1 * 256);
        const float4* Vd1 = reinterpret_cast<const float4*>(g_Vdst + (size_t)i1 * 256);

        // issue all 16 loads up-front (MLP)
        float4 a0c = A0[lane],      a0g = A0[lane + 32];
        float4 s0c = Vs0[lane],     s0g = Vs0[lane + 32];
        float4 e0c = Ep0[lane],     e0g = Ep0[lane + 32];
        float4 d0c = Vd0[lane],     d0g = Vd0[lane + 32];
        float4 a1c, a1g, s1c, s1g, e1c, e1g, d1c, d1g;
        if (h1) {
            a1c = A1[lane];  a1g = A1[lane + 32];
            s1c = Vs1[lane]; s1g = Vs1[lane + 32];
            e1c = Ep1[lane]; e1g = Ep1[lane + 32];
            d1c = Vd1[lane]; d1g = Vd1[lane + 32];
        }

        float4 c0 = f4add(f4add(a0c, s0c), f4add(e0c, d0c));
        float4 g0 = f4add(f4add(a0g, s0g), f4add(e0g, d0g));
        A0[lane] = c0;
        A0[lane + 32] = g0;
        sc = f4add(sc, c0);
        qc = f4add(qc, make_float4(c0.x * c0.x, c0.y * c0.y, c0.z * c0.z, c0.w * c0.w));
        sg = f4add(sg, g0);
        qg = f4add(qg, make_float4(g0.x * g0.x, g0.y * g0.y, g0.z * g0.z, g0.w * g0.w));

        if (h1) {
            float4 c1 = f4add(f4add(a1c, s1c), f4add(e1c, d1c));
            float4 g1 = f4add(f4add(a1g, s1g), f4add(e1g, d1g));
            A1[lane] = c1;
            A1[lane + 32] = g1;
            sc = f4add(sc, c1);
            qc = f4add(qc, make_float4(c1.x * c1.x, c1.y * c1.y, c1.z * c1.z, c1.w * c1.w));
            sg = f4add(sg, g1);
            qg = f4add(qg, make_float4(g1.x * g1.x, g1.y * g1.y, g1.z * g1.z, g1.w * g1.w));
        }
    }

    int c0i = lane * 4;
    atomicAdd(&g_stats[c0i + 0], sc.x); atomicAdd(&g_stats[c0i + 1], sc.y);
    atomicAdd(&g_stats[c0i + 2], sc.z); atomicAdd(&g_stats[c0i + 3], sc.w);
    atomicAdd(&g_stats[128 + c0i + 0], qc.x); atomicAdd(&g_stats[128 + c0i + 1], qc.y);
    atomicAdd(&g_stats[128 + c0i + 2], qc.z); atomicAdd(&g_stats[128 + c0i + 3], qc.w);
    atomicAdd(&g_stats[256 + c0i + 0], sg.x); atomicAdd(&g_stats[256 + c0i + 1], sg.y);
    atomicAdd(&g_stats[256 + c0i + 2], sg.z); atomicAdd(&g_stats[256 + c0i + 3], sg.w);
    atomicAdd(&g_stats[384 + c0i + 0], qg.x); atomicAdd(&g_stats[384 + c0i + 1], qg.y);
    atomicAdd(&g_stats[384 + c0i + 2], qg.z); atomicAdd(&g_stats[384 + c0i + 3], qg.w);
}

// ------------------------------------------------------------------
__global__ void finalize_stats(const float* __restrict__ gamC, const float* __restrict__ betC,
                               const float* __restrict__ gamG, const float* __restrict__ betG,
                               float invT) {
    int c = threadIdx.x;  // 128 threads
    float m = g_stats[c] * invT;
    float v = g_stats[128 + c] * invT - m * m;
    float a = rsqrtf(v + BN_EPS) * gamC[c];
    g_scale[c] = a;
    g_scale[128 + c] = betC[c] - m * a;

    m = g_stats[256 + c] * invT;
    v = g_stats[384 + c] * invT - m * m;
    a = rsqrtf(v + BN_EPS) * gamG[c];
    g_scale[256 + c] = a;
    g_scale[384 + c] = betG[c] - m * a;
}

// ------------------------------------------------------------------
__device__ __forceinline__ float sigf(float x) { return 1.0f / (1.0f + __expf(-x)); }

__global__ void pass_scatter(const int* __restrict__ kx, int T) {
    const int lane = threadIdx.x & 31;
    int warp = (blockIdx.x * blockDim.x + threadIdx.x) >> 5;
    const int nw = (gridDim.x * blockDim.x) >> 5;

    const float4 ac = reinterpret_cast<const float4*>(g_scale)[lane];
    const float4 bc = reinterpret_cast<const float4*>(g_scale + 128)[lane];
    const float4 ag = reinterpret_cast<const float4*>(g_scale + 256)[lane];
    const float4 bg = reinterpret_cast<const float4*>(g_scale + 384)[lane];

    for (int t0 = warp * 2; t0 < T; t0 += nw * 2) {
        int t1 = t0 + 1;
        bool h1 = t1 < T;
        int k0 = kx[t0];
        int k1 = h1 ? kx[t1] : k0;

        const float4* A0 = reinterpret_cast<const float4*>(g_A + (size_t)t0 * 256);
        const float4* A1 = reinterpret_cast<const float4*>(g_A + (size_t)t1 * 256);
        float4 c0 = A0[lane], g0 = A0[lane + 32];
        float4 c1, g1;
        if (h1) { c1 = A1[lane]; g1 = A1[lane + 32]; }

        {
            float cnx = c0.x * ac.x + bc.x, cny = c0.y * ac.y + bc.y;
            float cnz = c0.z * ac.z + bc.z, cnw = c0.w * ac.w + bc.w;
            float gnx = g0.x * ag.x + bg.x, gny = g0.y * ag.y + bg.y;
            float gnz = g0.z * ag.z + bg.z, gnw = g0.w * ag.w + bg.w;
            float* dst = g_seg + (size_t)k0 * 128 + lane * 4;
            atomicAdd(dst + 0, cnx * sigf(cnx) * sigf(gnx));
            atomicAdd(dst + 1, cny * sigf(cny) * sigf(gny));
            atomicAdd(dst + 2, cnz * sigf(cnz) * sigf(gnz));
            atomicAdd(dst + 3, cnw * sigf(cnw) * sigf(gnw));
        }
        if (h1) {
            float cnx = c1.x * ac.x + bc.x, cny = c1.y * ac.y + bc.y;
            float cnz = c1.z * ac.z + bc.z, cnw = c1.w * ac.w + bc.w;
            float gnx = g1.x * ag.x + bg.x, gny = g1.y * ag.y + bg.y;
            float gnz = g1.z * ag.z + bg.z, gnw = g1.w * ag.w + bg.w;
            float* dst = g_seg + (size_t)k1 * 128 + lane * 4;
            atomicAdd(dst + 0, cnx * sigf(cnx) * sigf(gnx));
            atomicAdd(dst + 1, cny * sigf(cny) * sigf(gny));
            atomicAdd(dst + 2, cnz * sigf(cnz) * sigf(gnz));
            atomicAdd(dst + 3, cnw * sigf(cnw) * sigf(gnw));
        }
    }
}

// ------------------------------------------------------------------
extern "C" void kernel_launch(void* const* d_in, const int* in_sizes, int n_in,
                              void* d_out, int out_size) {
    const float* vertex = (const float*)d_in[0];
    const float* edge   = (const float*)d_in[1];
    const float* angle  = (const float*)d_in[2];
    const int* kx = (const int*)d_in[4];
    const int* jx = (const int*)d_in[5];
    const int* ix = (const int*)d_in[6];
    const float* w_cs = (const float*)d_in[7];
    const float* w_cd = (const float*)d_in[8];
    const float* w_cb = (const float*)d_in[9];
    const float* w_ca = (const float*)d_in[10];
    const float* w_gs = (const float*)d_in[11];
    const float* w_gd = (const float*)d_in[12];
    const float* w_gb = (const float*)d_in[13];
    const float* w_ga = (const float*)d_in[14];
    const float* bcg = (const float*)d_in[15];
    const float* bcb = (const float*)d_in[16];
    const float* bgg = (const float*)d_in[17];
    const float* bgb = (const float*)d_in[18];
    const float* w_out = (const float*)d_in[19];

    const int N = in_sizes[0] / 128;
    const int E = in_sizes[1] / 128;
    const int T = in_sizes[2] / 64;

    float *pVsrc, *pVdst, *pEp, *pA, *pSeg, *pWv, *pWeb, *pWan;
    cudaGetSymbolAddress((void**)&pVsrc, g_Vsrc);
    cudaGetSymbolAddress((void**)&pVdst, g_Vdst);
    cudaGetSymbolAddress((void**)&pEp, g_Ep);
    cudaGetSymbolAddress((void**)&pA, g_A);
    cudaGetSymbolAddress((void**)&pSeg, g_seg);
    cudaGetSymbolAddress((void**)&pWv, g_Wv);
    cudaGetSymbolAddress((void**)&pWeb, g_Web);
    cudaGetSymbolAddress((void**)&pWan, g_Wan);

    const size_t smem_bytes = 2 * 128 * 68 * sizeof(float);  // 69632
    cudaFuncSetAttribute(mma_gemm<128>, cudaFuncAttributeMaxDynamicSharedMemorySize,
                         (int)smem_bytes);
    cudaFuncSetAttribute(mma_gemm<64>, cudaFuncAttributeMaxDynamicSharedMemorySize,
                         (int)smem_bytes);
    cudaFuncSetAttribute(mma_gemm_vertex, cudaFuncAttributeMaxDynamicSharedMemorySize,
                         (int)smem_bytes);

    zero_kernel<<<2048, 256>>>(E);
    pack_weights<<<64, 256>>>(w_cs, w_gs, pWv, 16384);           // rows 0-255
    pack_weights<<<64, 256>>>(w_cd, w_gd, pWv + 32768, 16384);   // rows 256-511
    pack_weights<<<64, 256>>>(w_cb, w_gb, pWeb, 16384);
    pack_weights<<<32, 256>>>(w_ca, w_ga, pWan, 8192);

    const int gN = (N + 127) / 128;
    const int gE = (E + 127) / 128;
    const int gT = (T + 127) / 128;

    // vertex: single launch, 4 output tiles (Vsrc core|gate, Vdst core|gate)
    mma_gemm_vertex<<<dim3(gN, 4), 256, smem_bytes>>>(vertex, pWv, pVsrc, pVdst, N);
    mma_gemm<128><<<dim3(gE, 2), 256, smem_bytes>>>(edge,  pWeb, nullptr, pEp, E, 256);
    mma_gemm<64> <<<dim3(gT, 2), 256, smem_bytes>>>(angle, pWan, nullptr, pA,  T, 256);

    // gather-add + BN stats (in-place over g_A), x2 unrolled
    pass_fuse<<<1184, 256>>>(kx, jx, ix, T);
    finalize_stats<<<1, 128>>>(bcg, bcb, bgg, bgb, 1.0f / (float)T);

    // activation + segment scatter, x2 unrolled
    pass_scatter<<<1184, 256>>>(kx, T);

    // new_bond = seg @ w_out.T + edge_feat
    mma_gemm<128><<<dim3(gE, 1), 256, smem_bytes>>>(pSeg, w_out, edge, (float*)d_out, E, 128);
}

// round 6
// speedup vs baseline: 1.2461x; 1.0633x over previous
#include <cuda_runtime.h>
#include <cuda_fp16.h>
#include <cstdint>

#define BN_EPS 1e-5f
#define MAXN 100000
#define MAXE 400000
#define MAXT 1000000

// ---- scratch (allocation-free, static device globals) ----
__device__ float g_Vsrc[(size_t)MAXN * 256];   // [N,256] = [core_src | gate_src]
__device__ float g_Vdst[(size_t)MAXN * 256];   // [N,256] = [core_dst | gate_dst]
__device__ float g_Ep  [(size_t)MAXE * 256];   // [E,256] = [core_bond | gate_bond]
__device__ float g_A   [(size_t)MAXT * 256];   // [T,256] fused core|gate (pre-BN)
__device__ float g_seg [(size_t)MAXE * 128];   // segment sums
__device__ float g_stats[512];                 // sumC | ssqC | sumG | ssqG
__device__ float g_scale[512];                 // aC | bC | aG | bG
__device__ float g_Wv [512 * 128];             // [w_core_src; w_gate_src; w_core_dst; w_gate_dst]
__device__ float g_Web[256 * 128];             // [w_core_bond ; w_gate_bond]
__device__ float g_Wan[256 * 64];              // [w_core_angle ; w_gate_angle]

// ------------------------------------------------------------------
__global__ void zero_kernel(int E) {
    size_t n4 = (size_t)E * 32;
    size_t i = (size_t)blockIdx.x * blockDim.x + threadIdx.x;
    size_t st = (size_t)gridDim.x * blockDim.x;
    float4 z = make_float4(0.f, 0.f, 0.f, 0.f);
    float4* p = reinterpret_cast<float4*>(g_seg);
    for (size_t k = i; k < n4; k += st) p[k] = z;
    if (i < 512) g_stats[i] = 0.f;
}

// pack [a;b] -> out [2*elems]
__global__ void pack_weights(const float* __restrict__ a, const float* __restrict__ b,
                             float* __restrict__ out, int elems) {
    int i = blockIdx.x * blockDim.x + threadIdx.x;
    if (i < elems) { out[i] = a[i]; out[elems + i] = b[i]; }
}

// ------------------------------------------------------------------
// fp16 mma.sync GEMM core (m16n8k16, fp32 accum). Computes a 128x128 tile:
// out[m, colBase + n] = X[row0+m, :] . W[wBase + n, :]  (+ Dadd)
// smem rows: 72 halves (36 words) -> conflict-free fragment LDS.
// ------------------------------------------------------------------
template<int K>
__device__ __forceinline__
void gemm_tile(const float* __restrict__ X, const float* __restrict__ W,
               const float* __restrict__ Dadd, float* __restrict__ C,
               int M, int ldc, int row0, int wBase, int colBase, char* smemc) {
    constexpr int BK = 64;
    constexpr int KP = 72;                 // halves per row (stride 36 words)
    __half* Xs = reinterpret_cast<__half*>(smemc);
    __half* Ws = Xs + 128 * KP;

    const int tid = threadIdx.x;
    const int lane = tid & 31;
    const int wid = tid >> 5;
    const int warpM = wid >> 2;
    const int warpN = wid & 3;
    const int g = lane >> 2;
    const int qc = lane & 3;

    float c[4][4][4];
#pragma unroll
    for (int mf = 0; mf < 4; ++mf)
#pragma unroll
        for (int nf = 0; nf < 4; ++nf)
#pragma unroll
            for (int q = 0; q < 4; ++q) c[mf][nf][q] = 0.f;

    for (int kt = 0; kt < K; kt += BK) {
        // X tile: fp32 global -> fp16 smem
        for (int i = tid; i < 128 * (BK / 4); i += 256) {
            int r = i >> 4;
            int k4 = (i & 15) << 2;
            int gr = row0 + r;
            float4 v = make_float4(0.f, 0.f, 0.f, 0.f);
            if (gr < M) v = *reinterpret_cast<const float4*>(X + (size_t)gr * K + kt + k4);
            __half2 h0 = __floats2half2_rn(v.x, v.y);
            __half2 h1 = __floats2half2_rn(v.z, v.w);
            uint2 u = make_uint2(*reinterpret_cast<uint32_t*>(&h0),
                                 *reinterpret_cast<uint32_t*>(&h1));
            *reinterpret_cast<uint2*>(Xs + r * KP + k4) = u;
        }
        // W tile
        for (int i = tid; i < 128 * (BK / 4); i += 256) {
            int r = i >> 4;
            int k4 = (i & 15) << 2;
            float4 v = *reinterpret_cast<const float4*>(W + (size_t)(wBase + r) * K + kt + k4);
            __half2 h0 = __floats2half2_rn(v.x, v.y);
            __half2 h1 = __floats2half2_rn(v.z, v.w);
            uint2 u = make_uint2(*reinterpret_cast<uint32_t*>(&h0),
                                 *reinterpret_cast<uint32_t*>(&h1));
            *reinterpret_cast<uint2*>(Ws + r * KP + k4) = u;
        }
        __syncthreads();

        const uint32_t* Xu = reinterpret_cast<const uint32_t*>(Xs);
        const uint32_t* Wu = reinterpret_cast<const uint32_t*>(Ws);
#pragma unroll
        for (int k0 = 0; k0 < BK; k0 += 16) {
            const int kw = k0 >> 1;        // word offset
            uint32_t a[4][4], b[4][2];
#pragma unroll
            for (int mf = 0; mf < 4; ++mf) {
                int r = warpM * 64 + mf * 16 + g;
                a[mf][0] = Xu[r * 36 + kw + qc];
                a[mf][1] = Xu[(r + 8) * 36 + kw + qc];
                a[mf][2] = Xu[r * 36 + kw + 4 + qc];
                a[mf][3] = Xu[(r + 8) * 36 + kw + 4 + qc];
            }
#pragma unroll
            for (int nf = 0; nf < 4; ++nf) {
                int n = warpN * 32 + nf * 8 + g;
                b[nf][0] = Wu[n * 36 + kw + qc];
                b[nf][1] = Wu[n * 36 + kw + 4 + qc];
            }
#pragma unroll
            for (int mf = 0; mf < 4; ++mf)
#pragma unroll
                for (int nf = 0; nf < 4; ++nf) {
                    asm volatile(
                        "mma.sync.aligned.m16n8k16.row.col.f32.f16.f16.f32 "
                        "{%0,%1,%2,%3}, {%4,%5,%6,%7}, {%8,%9}, {%0,%1,%2,%3};"
                        : "+f"(c[mf][nf][0]), "+f"(c[mf][nf][1]),
                          "+f"(c[mf][nf][2]), "+f"(c[mf][nf][3])
                        : "r"(a[mf][0]), "r"(a[mf][1]), "r"(a[mf][2]), "r"(a[mf][3]),
                          "r"(b[nf][0]), "r"(b[nf][1]));
                }
        }
        __syncthreads();
    }

#pragma unroll
    for (int mf = 0; mf < 4; ++mf) {
        int r0 = row0 + warpM * 64 + mf * 16 + g;
        int r1 = r0 + 8;
#pragma unroll
        for (int nf = 0; nf < 4; ++nf) {
            int col = colBase + warpN * 32 + nf * 8 + qc * 2;
            if (r0 < M) {
                float2 o = make_float2(c[mf][nf][0], c[mf][nf][1]);
                if (Dadd) {
                    float2 d = *reinterpret_cast<const float2*>(Dadd + (size_t)r0 * ldc + col);
                    o.x += d.x; o.y += d.y;
                }
                *reinterpret_cast<float2*>(C + (size_t)r0 * ldc + col) = o;
            }
            if (r1 < M) {
                float2 o = make_float2(c[mf][nf][2], c[mf][nf][3]);
                if (Dadd) {
                    float2 d = *reinterpret_cast<const float2*>(Dadd + (size_t)r1 * ldc + col);
                    o.x += d.x; o.y += d.y;
                }
                *reinterpret_cast<float2*>(C + (size_t)r1 * ldc + col) = o;
            }
        }
    }
}

template<int K>
__global__ __launch_bounds__(256, 2)
void mma_gemm(const float* __restrict__ X, const float* __restrict__ W,
              const float* __restrict__ Dadd, float* __restrict__ C,
              int M, int ldc) {
    extern __shared__ char smemc[];
    gemm_tile<K>(X, W, Dadd, C, M, ldc, blockIdx.x * 128,
                 blockIdx.y * 128, blockIdx.y * 128, smemc);
}

// merged vertex GEMM: y in 0..3 -> [Vsrc core, Vsrc gate, Vdst core, Vdst gate]
__global__ __launch_bounds__(256, 2)
void mma_gemm_vertex(const float* __restrict__ X, const float* __restrict__ W,
                     float* __restrict__ C0, float* __restrict__ C1, int M) {
    extern __shared__ char smemc[];
    int y = blockIdx.y;
    float* C = (y < 2) ? C0 : C1;
    gemm_tile<128>(X, W, nullptr, C, M, 256, blockIdx.x * 128,
                   y * 128, (y & 1) * 128, smemc);
}

// ------------------------------------------------------------------
// pass B: core/gate = A + Vsrc[j] + Ep[k] + Vdst[i] (in place), + BN stats.
// ------------------------------------------------------------------
__device__ __forceinline__ float4 f4add(float4 a, float4 b) {
    return make_float4(a.x + b.x, a.y + b.y, a.z + b.z, a.w + b.w);
}

__global__ void pass_fuse(const int* __restrict__ kx, const int* __restrict__ jx,
                          const int* __restrict__ ix, int T) {
    const int lane = threadIdx.x & 31;
    int warp = (blockIdx.x * blockDim.x + threadIdx.x) >> 5;
    const int nw = (gridDim.x * blockDim.x) >> 5;

    float4 sc = make_float4(0, 0, 0, 0), qc = make_float4(0, 0, 0, 0);
    float4 sg = make_float4(0, 0, 0, 0), qg = make_float4(0, 0, 0, 0);

    for (int t0 = warp * 2; t0 < T; t0 += nw * 2) {
        int t1 = t0 + 1;
        bool h1 = t1 < T;
        int j0 = jx[t0], k0 = kx[t0], i0 = ix[t0];
        int j1 = h1 ? jx[t1] : j0, k1 = h1 ? kx[t1] : k0, i1 = h1 ? ix[t1] : i0;

        float4* A0 = reinterpret_cast<float4*>(g_A + (size_t)t0 * 256);
        float4* A1 = reinterpret_cast<float4*>(g_A + (size_t)t1 * 256);
        const float4* Vs0 = reinterpret_cast<const float4*>(g_Vsrc + (size_t)j0 * 256);
        const float4* Ep0 = reinterpret_cast<const float4*>(g_Ep + (size_t)k0 * 256);
        const float4* Vd0 = reinterpret_cast<const float4*>(g_Vdst + (size_t)i0 * 256);
        const float4* Vs1 = reinterpret_cast<const float4*>(g_Vsrc + (size_t)j1 * 256);
        const float4* Ep1 = reinterpret_cast<const float4*>(g_Ep + (size_t)k1 * 256);
        const float4* Vd1 = reinterpret_cast<const float4*>(g_Vdst + (size_t)i1 * 256);

        float4 a0c = A0[lane],      a0g = A0[lane + 32];
        float4 s0c = Vs0[lane],     s0g = Vs0[lane + 32];
        float4 e0c = Ep0[lane],     e0g = Ep0[lane + 32];
        float4 d0c = Vd0[lane],     d0g = Vd0[lane + 32];
        float4 a1c, a1g, s1c, s1g, e1c, e1g, d1c, d1g;
        if (h1) {
            a1c = A1[lane];  a1g = A1[lane + 32];
            s1c = Vs1[lane]; s1g = Vs1[lane + 32];
            e1c = Ep1[lane]; e1g = Ep1[lane + 32];
            d1c = Vd1[lane]; d1g = Vd1[lane + 32];
        }

        float4 c0 = f4add(f4add(a0c, s0c), f4add(e0c, d0c));
        float4 g0 = f4add(f4add(a0g, s0g), f4add(e0g, d0g));
        A0[lane] = c0;
        A0[lane + 32] = g0;
        sc = f4add(sc, c0);
        qc = f4add(qc, make_float4(c0.x * c0.x, c0.y * c0.y, c0.z * c0.z, c0.w * c0.w));
        sg = f4add(sg, g0);
        qg = f4add(qg, make_float4(g0.x * g0.x, g0.y * g0.y, g0.z * g0.z, g0.w * g0.w));

        if (h1) {
            float4 c1 = f4add(f4add(a1c, s1c), f4add(e1c, d1c));
            float4 g1 = f4add(f4add(a1g, s1g), f4add(e1g, d1g));
            A1[lane] = c1;
            A1[lane + 32] = g1;
            sc = f4add(sc, c1);
            qc = f4add(qc, make_float4(c1.x * c1.x, c1.y * c1.y, c1.z * c1.z, c1.w * c1.w));
            sg = f4add(sg, g1);
            qg = f4add(qg, make_float4(g1.x * g1.x, g1.y * g1.y, g1.z * g1.z, g1.w * g1.w));
        }
    }

    int c0i = lane * 4;
    atomicAdd(&g_stats[c0i + 0], sc.x); atomicAdd(&g_stats[c0i + 1], sc.y);
    atomicAdd(&g_stats[c0i + 2], sc.z); atomicAdd(&g_stats[c0i + 3], sc.w);
    atomicAdd(&g_stats[128 + c0i + 0], qc.x); atomicAdd(&g_stats[128 + c0i + 1], qc.y);
    atomicAdd(&g_stats[128 + c0i + 2], qc.z); atomicAdd(&g_stats[128 + c0i + 3], qc.w);
    atomicAdd(&g_stats[256 + c0i + 0], sg.x); atomicAdd(&g_stats[256 + c0i + 1], sg.y);
    atomicAdd(&g_stats[256 + c0i + 2], sg.z); atomicAdd(&g_stats[256 + c0i + 3], sg.w);
    atomicAdd(&g_stats[384 + c0i + 0], qg.x); atomicAdd(&g_stats[384 + c0i + 1], qg.y);
    atomicAdd(&g_stats[384 + c0i + 2], qg.z); atomicAdd(&g_stats[384 + c0i + 3], qg.w);
}

// ------------------------------------------------------------------
__global__ void finalize_stats(const float* __restrict__ gamC, const float* __restrict__ betC,
                               const float* __restrict__ gamG, const float* __restrict__ betG,
                               float invT) {
    int c = threadIdx.x;  // 128 threads
    float m = g_stats[c] * invT;
    float v = g_stats[128 + c] * invT - m * m;
    float a = rsqrtf(v + BN_EPS) * gamC[c];
    g_scale[c] = a;
    g_scale[128 + c] = betC[c] - m * a;

    m = g_stats[256 + c] * invT;
    v = g_stats[384 + c] * invT - m * m;
    a = rsqrtf(v + BN_EPS) * gamG[c];
    g_scale[256 + c] = a;
    g_scale[384 + c] = betG[c] - m * a;
}

// ------------------------------------------------------------------
__device__ __forceinline__ float sigf(float x) { return 1.0f / (1.0f + __expf(-x)); }

__global__ void pass_scatter(const int* __restrict__ kx, int T) {
    const int lane = threadIdx.x & 31;
    int warp = (blockIdx.x * blockDim.x + threadIdx.x) >> 5;
    const int nw = (gridDim.x * blockDim.x) >> 5;

    const float4 ac = reinterpret_cast<const float4*>(g_scale)[lane];
    const float4 bc = reinterpret_cast<const float4*>(g_scale + 128)[lane];
    const float4 ag = reinterpret_cast<const float4*>(g_scale + 256)[lane];
    const float4 bg = reinterpret_cast<const float4*>(g_scale + 384)[lane];

    for (int t0 = warp * 2; t0 < T; t0 += nw * 2) {
        int t1 = t0 + 1;
        bool h1 = t1 < T;
        int k0 = kx[t0];
        int k1 = h1 ? kx[t1] : k0;

        const float4* A0 = reinterpret_cast<const float4*>(g_A + (size_t)t0 * 256);
        const float4* A1 = reinterpret_cast<const float4*>(g_A + (size_t)t1 * 256);
        float4 c0 = A0[lane], g0 = A0[lane + 32];
        float4 c1, g1;
        if (h1) { c1 = A1[lane]; g1 = A1[lane + 32]; }

        {
            float cnx = c0.x * ac.x + bc.x, cny = c0.y * ac.y + bc.y;
            float cnz = c0.z * ac.z + bc.z, cnw = c0.w * ac.w + bc.w;
            float gnx = g0.x * ag.x + bg.x, gny = g0.y * ag.y + bg.y;
            float gnz = g0.z * ag.z + bg.z, gnw = g0.w * ag.w + bg.w;
            float* dst = g_seg + (size_t)k0 * 128 + lane * 4;
            atomicAdd(dst + 0, cnx * sigf(cnx) * sigf(gnx));
            atomicAdd(dst + 1, cny * sigf(cny) * sigf(gny));
            atomicAdd(dst + 2, cnz * sigf(cnz) * sigf(gnz));
            atomicAdd(dst + 3, cnw * sigf(cnw) * sigf(gnw));
        }
        if (h1) {
            float cnx = c1.x * ac.x + bc.x, cny = c1.y * ac.y + bc.y;
            float cnz = c1.z * ac.z + bc.z, cnw = c1.w * ac.w + bc.w;
            float gnx = g1.x * ag.x + bg.x, gny = g1.y * ag.y + bg.y;
            float gnz = g1.z * ag.z + bg.z, gnw = g1.w * ag.w + bg.w;
            float* dst = g_seg + (size_t)k1 * 128 + lane * 4;
            atomicAdd(dst + 0, cnx * sigf(cnx) * sigf(gnx));
            atomicAdd(dst + 1, cny * sigf(cny) * sigf(gny));
            atomicAdd(dst + 2, cnz * sigf(cnz) * sigf(gnz));
            atomicAdd(dst + 3, cnw * sigf(cnw) * sigf(gnw));
        }
    }
}

// ------------------------------------------------------------------
extern "C" void kernel_launch(void* const* d_in, const int* in_sizes, int n_in,
                              void* d_out, int out_size) {
    const float* vertex = (const float*)d_in[0];
    const float* edge   = (const float*)d_in[1];
    const float* angle  = (const float*)d_in[2];
    const int* kx = (const int*)d_in[4];
    const int* jx = (const int*)d_in[5];
    const int* ix = (const int*)d_in[6];
    const float* w_cs = (const float*)d_in[7];
    const float* w_cd = (const float*)d_in[8];
    const float* w_cb = (const float*)d_in[9];
    const float* w_ca = (const float*)d_in[10];
    const float* w_gs = (const float*)d_in[11];
    const float* w_gd = (const float*)d_in[12];
    const float* w_gb = (const float*)d_in[13];
    const float* w_ga = (const float*)d_in[14];
    const float* bcg = (const float*)d_in[15];
    const float* bcb = (const float*)d_in[16];
    const float* bgg = (const float*)d_in[17];
    const float* bgb = (const float*)d_in[18];
    const float* w_out = (const float*)d_in[19];

    const int N = in_sizes[0] / 128;
    const int E = in_sizes[1] / 128;
    const int T = in_sizes[2] / 64;

    float *pVsrc, *pVdst, *pEp, *pA, *pSeg, *pWv, *pWeb, *pWan;
    cudaGetSymbolAddress((void**)&pVsrc, g_Vsrc);
    cudaGetSymbolAddress((void**)&pVdst, g_Vdst);
    cudaGetSymbolAddress((void**)&pEp, g_Ep);
    cudaGetSymbolAddress((void**)&pA, g_A);
    cudaGetSymbolAddress((void**)&pSeg, g_seg);
    cudaGetSymbolAddress((void**)&pWv, g_Wv);
    cudaGetSymbolAddress((void**)&pWeb, g_Web);
    cudaGetSymbolAddress((void**)&pWan, g_Wan);

    const size_t smem_bytes = 2 * 128 * 72 * sizeof(__half);  // 36864
    cudaFuncSetAttribute(mma_gemm<128>, cudaFuncAttributeMaxDynamicSharedMemorySize,
                         (int)smem_bytes);
    cudaFuncSetAttribute(mma_gemm<64>, cudaFuncAttributeMaxDynamicSharedMemorySize,
                         (int)smem_bytes);
    cudaFuncSetAttribute(mma_gemm_vertex, cudaFuncAttributeMaxDynamicSharedMemorySize,
                         (int)smem_bytes);

    zero_kernel<<<2048, 256>>>(E);
    pack_weights<<<64, 256>>>(w_cs, w_gs, pWv, 16384);           // rows 0-255
    pack_weights<<<64, 256>>>(w_cd, w_gd, pWv + 32768, 16384);   // rows 256-511
    pack_weights<<<64, 256>>>(w_cb, w_gb, pWeb, 16384);
    pack_weights<<<32, 256>>>(w_ca, w_ga, pWan, 8192);

    const int gN = (N + 127) / 128;
    const int gE = (E + 127) / 128;
    const int gT = (T + 127) / 128;

    // vertex: single launch, 4 output tiles (Vsrc core|gate, Vdst core|gate)
    mma_gemm_vertex<<<dim3(gN, 4), 256, smem_bytes>>>(vertex, pWv, pVsrc, pVdst, N);
    mma_gemm<128><<<dim3(gE, 2), 256, smem_bytes>>>(edge,  pWeb, nullptr, pEp, E, 256);
    mma_gemm<64> <<<dim3(gT, 2), 256, smem_bytes>>>(angle, pWan, nullptr, pA,  T, 256);

    // gather-add + BN stats (in-place over g_A), x2 unrolled
    pass_fuse<<<1184, 256>>>(kx, jx, ix, T);
    finalize_stats<<<1, 128>>>(bcg, bcb, bgg, bgb, 1.0f / (float)T);

    // activation + segment scatter, x2 unrolled
    pass_scatter<<<1184, 256>>>(kx, T);

    // new_bond = seg @ w_out.T + edge_feat
    mma_gemm<128><<<dim3(gE, 1), 256, smem_bytes>>>(pSeg, w_out, edge, (float*)d_out, E, 128);
}

// round 7
// speedup vs baseline: 1.4565x; 1.1689x over previous
#include <cuda_runtime.h>
#include <cuda_fp16.h>
#include <cstdint>

#define BN_EPS 1e-5f
#define MAXN 100000
#define MAXE 400000
#define MAXT 1000000

// ---- scratch (allocation-free, static device globals) ----
__device__ __half g_Vsrc[(size_t)MAXN * 256];  // [N,256] = [core_src | gate_src]
__device__ __half g_Vdst[(size_t)MAXN * 256];  // [N,256] = [core_dst | gate_dst]
__device__ __half g_Ep  [(size_t)MAXE * 256];  // [E,256] = [core_bond | gate_bond]
__device__ __half g_A   [(size_t)MAXT * 256];  // [T,256] fused core|gate (pre-BN)
__device__ float  g_seg [(size_t)MAXE * 128];  // segment sums (fp32 atomics)
__device__ float  g_stats[512];                // sumC | ssqC | sumG | ssqG
__device__ float  g_scale[512];                // aC | bC | aG | bG
__device__ float  g_Wv [512 * 128];            // [w_core_src; w_gate_src; w_core_dst; w_gate_dst]
__device__ float  g_Web[256 * 128];            // [w_core_bond ; w_gate_bond]
__device__ float  g_Wan[256 * 64];             // [w_core_angle ; w_gate_angle]

// ------------------------------------------------------------------
__global__ void zero_kernel(int E) {
    size_t n4 = (size_t)E * 32;
    size_t i = (size_t)blockIdx.x * blockDim.x + threadIdx.x;
    size_t st = (size_t)gridDim.x * blockDim.x;
    float4 z = make_float4(0.f, 0.f, 0.f, 0.f);
    float4* p = reinterpret_cast<float4*>(g_seg);
    for (size_t k = i; k < n4; k += st) p[k] = z;
    if (i < 512) g_stats[i] = 0.f;
}

// pack [a;b] -> out [2*elems]
__global__ void pack_weights(const float* __restrict__ a, const float* __restrict__ b,
                             float* __restrict__ out, int elems) {
    int i = blockIdx.x * blockDim.x + threadIdx.x;
    if (i < elems) { out[i] = a[i]; out[elems + i] = b[i]; }
}

// ---- fp16 row helpers: 4 halves per lane slot ----
__device__ __forceinline__ float4 ldh4(const __half* p) {
    uint2 u = *reinterpret_cast<const uint2*>(p);
    __half2 h0 = *reinterpret_cast<__half2*>(&u.x);
    __half2 h1 = *reinterpret_cast<__half2*>(&u.y);
    float2 f0 = __half22float2(h0);
    float2 f1 = __half22float2(h1);
    return make_float4(f0.x, f0.y, f1.x, f1.y);
}
__device__ __forceinline__ void sth4(__half* p, float4 v) {
    __half2 h0 = __floats2half2_rn(v.x, v.y);
    __half2 h1 = __floats2half2_rn(v.z, v.w);
    uint2 u = make_uint2(*reinterpret_cast<uint32_t*>(&h0),
                         *reinterpret_cast<uint32_t*>(&h1));
    *reinterpret_cast<uint2*>(p) = u;
}

// ------------------------------------------------------------------
// fp16 mma.sync GEMM core (m16n8k16, fp32 accum). 128x128 tile:
// out[m, colBase + n] = X[row0+m, :] . W[wBase + n, :]  (+ Dadd, fp32 out only)
// ------------------------------------------------------------------
template<int K, typename OutT>
__device__ __forceinline__
void gemm_tile(const float* __restrict__ X, const float* __restrict__ W,
               const float* __restrict__ Dadd, OutT* __restrict__ C,
               int M, int ldc, int row0, int wBase, int colBase, char* smemc) {
    constexpr int BK = 64;
    constexpr int KP = 72;                 // halves per row (36 words)
    __half* Xs = reinterpret_cast<__half*>(smemc);
    __half* Ws = Xs + 128 * KP;

    const int tid = threadIdx.x;
    const int lane = tid & 31;
    const int wid = tid >> 5;
    const int warpM = wid >> 2;
    const int warpN = wid & 3;
    const int g = lane >> 2;
    const int qc = lane & 3;

    float c[4][4][4];
#pragma unroll
    for (int mf = 0; mf < 4; ++mf)
#pragma unroll
        for (int nf = 0; nf < 4; ++nf)
#pragma unroll
            for (int q = 0; q < 4; ++q) c[mf][nf][q] = 0.f;

    for (int kt = 0; kt < K; kt += BK) {
        for (int i = tid; i < 128 * (BK / 4); i += 256) {
            int r = i >> 4;
            int k4 = (i & 15) << 2;
            int gr = row0 + r;
            float4 v = make_float4(0.f, 0.f, 0.f, 0.f);
            if (gr < M) v = *reinterpret_cast<const float4*>(X + (size_t)gr * K + kt + k4);
            __half2 h0 = __floats2half2_rn(v.x, v.y);
            __half2 h1 = __floats2half2_rn(v.z, v.w);
            uint2 u = make_uint2(*reinterpret_cast<uint32_t*>(&h0),
                                 *reinterpret_cast<uint32_t*>(&h1));
            *reinterpret_cast<uint2*>(Xs + r * KP + k4) = u;
        }
        for (int i = tid; i < 128 * (BK / 4); i += 256) {
            int r = i >> 4;
            int k4 = (i & 15) << 2;
            float4 v = *reinterpret_cast<const float4*>(W + (size_t)(wBase + r) * K + kt + k4);
            __half2 h0 = __floats2half2_rn(v.x, v.y);
            __half2 h1 = __floats2half2_rn(v.z, v.w);
            uint2 u = make_uint2(*reinterpret_cast<uint32_t*>(&h0),
                                 *reinterpret_cast<uint32_t*>(&h1));
            *reinterpret_cast<uint2*>(Ws + r * KP + k4) = u;
        }
        __syncthreads();

        const uint32_t* Xu = reinterpret_cast<const uint32_t*>(Xs);
        const uint32_t* Wu = reinterpret_cast<const uint32_t*>(Ws);
#pragma unroll
        for (int k0 = 0; k0 < BK; k0 += 16) {
            const int kw = k0 >> 1;
            uint32_t a[4][4], b[4][2];
#pragma unroll
            for (int mf = 0; mf < 4; ++mf) {
                int r = warpM * 64 + mf * 16 + g;
                a[mf][0] = Xu[r * 36 + kw + qc];
                a[mf][1] = Xu[(r + 8) * 36 + kw + qc];
                a[mf][2] = Xu[r * 36 + kw + 4 + qc];
                a[mf][3] = Xu[(r + 8) * 36 + kw + 4 + qc];
            }
#pragma unroll
            for (int nf = 0; nf < 4; ++nf) {
                int n = warpN * 32 + nf * 8 + g;
                b[nf][0] = Wu[n * 36 + kw + qc];
                b[nf][1] = Wu[n * 36 + kw + 4 + qc];
            }
#pragma unroll
            for (int mf = 0; mf < 4; ++mf)
#pragma unroll
                for (int nf = 0; nf < 4; ++nf) {
                    asm volatile(
                        "mma.sync.aligned.m16n8k16.row.col.f32.f16.f16.f32 "
                        "{%0,%1,%2,%3}, {%4,%5,%6,%7}, {%8,%9}, {%0,%1,%2,%3};"
                        : "+f"(c[mf][nf][0]), "+f"(c[mf][nf][1]),
                          "+f"(c[mf][nf][2]), "+f"(c[mf][nf][3])
                        : "r"(a[mf][0]), "r"(a[mf][1]), "r"(a[mf][2]), "r"(a[mf][3]),
                          "r"(b[nf][0]), "r"(b[nf][1]));
                }
        }
        __syncthreads();
    }

#pragma unroll
    for (int mf = 0; mf < 4; ++mf) {
        int r0 = row0 + warpM * 64 + mf * 16 + g;
        int r1 = r0 + 8;
#pragma unroll
        for (int nf = 0; nf < 4; ++nf) {
            int col = colBase + warpN * 32 + nf * 8 + qc * 2;
#pragma unroll
            for (int half = 0; half < 2; ++half) {
                int r = half ? r1 : r0;
                if (r >= M) continue;
                float ox = c[mf][nf][half * 2 + 0];
                float oy = c[mf][nf][half * 2 + 1];
                if constexpr (sizeof(OutT) == 4) {
                    if (Dadd) {
                        float2 d = *reinterpret_cast<const float2*>(
                            Dadd + (size_t)r * ldc + col);
                        ox += d.x; oy += d.y;
                    }
                    *reinterpret_cast<float2*>(
                        reinterpret_cast<float*>(C) + (size_t)r * ldc + col) =
                        make_float2(ox, oy);
                } else {
                    __half2 h = __floats2half2_rn(ox, oy);
                    *reinterpret_cast<__half2*>(
                        reinterpret_cast<__half*>(C) + (size_t)r * ldc + col) = h;
                }
            }
        }
    }
}

template<int K, typename OutT>
__global__ __launch_bounds__(256, 2)
void mma_gemm(const float* __restrict__ X, const float* __restrict__ W,
              const float* __restrict__ Dadd, OutT* __restrict__ C,
              int M, int ldc) {
    extern __shared__ char smemc[];
    gemm_tile<K, OutT>(X, W, Dadd, C, M, ldc, blockIdx.x * 128,
                       blockIdx.y * 128, blockIdx.y * 128, smemc);
}

// merged vertex GEMM: y in 0..3 -> [Vsrc core, Vsrc gate, Vdst core, Vdst gate]
__global__ __launch_bounds__(256, 2)
void mma_gemm_vertex(const float* __restrict__ X, const float* __restrict__ W,
                     __half* __restrict__ C0, __half* __restrict__ C1, int M) {
    extern __shared__ char smemc[];
    int y = blockIdx.y;
    __half* C = (y < 2) ? C0 : C1;
    gemm_tile<128, __half>(X, W, nullptr, C, M, 256, blockIdx.x * 128,
                           y * 128, (y & 1) * 128, smemc);
}

// ------------------------------------------------------------------
// pass B: core/gate = A + Vsrc[j] + Ep[k] + Vdst[i] (in place, fp16), + BN stats.
// ------------------------------------------------------------------
__device__ __forceinline__ float4 f4add(float4 a, float4 b) {
    return make_float4(a.x + b.x, a.y + b.y, a.z + b.z, a.w + b.w);
}

__global__ void pass_fuse(const int* __restrict__ kx, const int* __restrict__ jx,
                          const int* __restrict__ ix, int T) {
    const int lane = threadIdx.x & 31;
    int warp = (blockIdx.x * blockDim.x + threadIdx.x) >> 5;
    const int nw = (gridDim.x * blockDim.x) >> 5;
    const int c4 = lane * 4;

    float4 sc = make_float4(0, 0, 0, 0), qc = make_float4(0, 0, 0, 0);
    float4 sg = make_float4(0, 0, 0, 0), qg = make_float4(0, 0, 0, 0);

    for (int t0 = warp * 2; t0 < T; t0 += nw * 2) {
        int t1 = t0 + 1;
        bool h1 = t1 < T;
        int j0 = jx[t0], k0 = kx[t0], i0 = ix[t0];
        int j1 = h1 ? jx[t1] : j0, k1 = h1 ? kx[t1] : k0, i1 = h1 ? ix[t1] : i0;

        __half* A0 = g_A + (size_t)t0 * 256;
        __half* A1 = g_A + (size_t)t1 * 256;
        const __half* Vs0 = g_Vsrc + (size_t)j0 * 256;
        const __half* Ep0 = g_Ep   + (size_t)k0 * 256;
        const __half* Vd0 = g_Vdst + (size_t)i0 * 256;
        const __half* Vs1 = g_Vsrc + (size_t)j1 * 256;
        const __half* Ep1 = g_Ep   + (size_t)k1 * 256;
        const __half* Vd1 = g_Vdst + (size_t)i1 * 256;

        float4 a0c = ldh4(A0 + c4),        a0g = ldh4(A0 + 128 + c4);
        float4 s0c = ldh4(Vs0 + c4),       s0g = ldh4(Vs0 + 128 + c4);
        float4 e0c = ldh4(Ep0 + c4),       e0g = ldh4(Ep0 + 128 + c4);
        float4 d0c = ldh4(Vd0 + c4),       d0g = ldh4(Vd0 + 128 + c4);
        float4 a1c, a1g, s1c, s1g, e1c, e1g, d1c, d1g;
        if (h1) {
            a1c = ldh4(A1 + c4);  a1g = ldh4(A1 + 128 + c4);
            s1c = ldh4(Vs1 + c4); s1g = ldh4(Vs1 + 128 + c4);
            e1c = ldh4(Ep1 + c4); e1g = ldh4(Ep1 + 128 + c4);
            d1c = ldh4(Vd1 + c4); d1g = ldh4(Vd1 + 128 + c4);
        }

        {
            float4 c0 = f4add(f4add(a0c, s0c), f4add(e0c, d0c));
            float4 g0 = f4add(f4add(a0g, s0g), f4add(e0g, d0g));
            sth4(A0 + c4, c0);
            sth4(A0 + 128 + c4, g0);
            // stats from the stored (rounded) values for self-consistency
            c0 = ldh4(A0 + c4); g0 = ldh4(A0 + 128 + c4);
            sc = f4add(sc, c0);
            qc = f4add(qc, make_float4(c0.x * c0.x, c0.y * c0.y, c0.z * c0.z, c0.w * c0.w));
            sg = f4add(sg, g0);
            qg = f4add(qg, make_float4(g0.x * g0.x, g0.y * g0.y, g0.z * g0.z, g0.w * g0.w));
        }
        if (h1) {
            float4 c1 = f4add(f4add(a1c, s1c), f4add(e1c, d1c));
            float4 g1 = f4add(f4add(a1g, s1g), f4add(e1g, d1g));
            sth4(A1 + c4, c1);
            sth4(A1 + 128 + c4, g1);
            c1 = ldh4(A1 + c4); g1 = ldh4(A1 + 128 + c4);
            sc = f4add(sc, c1);
            qc = f4add(qc, make_float4(c1.x * c1.x, c1.y * c1.y, c1.z * c1.z, c1.w * c1.w));
            sg = f4add(sg, g1);
            qg = f4add(qg, make_float4(g1.x * g1.x, g1.y * g1.y, g1.z * g1.z, g1.w * g1.w));
        }
    }

    atomicAdd(&g_stats[c4 + 0], sc.x); atomicAdd(&g_stats[c4 + 1], sc.y);
    atomicAdd(&g_stats[c4 + 2], sc.z); atomicAdd(&g_stats[c4 + 3], sc.w);
    atomicAdd(&g_stats[128 + c4 + 0], qc.x); atomicAdd(&g_stats[128 + c4 + 1], qc.y);
    atomicAdd(&g_stats[128 + c4 + 2], qc.z); atomicAdd(&g_stats[128 + c4 + 3], qc.w);
    atomicAdd(&g_stats[256 + c4 + 0], sg.x); atomicAdd(&g_stats[256 + c4 + 1], sg.y);
    atomicAdd(&g_stats[256 + c4 + 2], sg.z); atomicAdd(&g_stats[256 + c4 + 3], sg.w);
    atomicAdd(&g_stats[384 + c4 + 0], qg.x); atomicAdd(&g_stats[384 + c4 + 1], qg.y);
    atomicAdd(&g_stats[384 + c4 + 2], qg.z); atomicAdd(&g_stats[384 + c4 + 3], qg.w);
}

// ------------------------------------------------------------------
__global__ void finalize_stats(const float* __restrict__ gamC, const float* __restrict__ betC,
                               const float* __restrict__ gamG, const float* __restrict__ betG,
                               float invT) {
    int c = threadIdx.x;  // 128 threads
    float m = g_stats[c] * invT;
    float v = g_stats[128 + c] * invT - m * m;
    float a = rsqrtf(v + BN_EPS) * gamC[c];
    g_scale[c] = a;
    g_scale[128 + c] = betC[c] - m * a;

    m = g_stats[256 + c] * invT;
    v = g_stats[384 + c] * invT - m * m;
    a = rsqrtf(v + BN_EPS) * gamG[c];
    g_scale[256 + c] = a;
    g_scale[384 + c] = betG[c] - m * a;
}

// ------------------------------------------------------------------
__device__ __forceinline__ float sigf(float x) { return 1.0f / (1.0f + __expf(-x)); }

__global__ void pass_scatter(const int* __restrict__ kx, int T) {
    const int lane = threadIdx.x & 31;
    int warp = (blockIdx.x * blockDim.x + threadIdx.x) >> 5;
    const int nw = (gridDim.x * blockDim.x) >> 5;
    const int c4 = lane * 4;

    const float4 ac = reinterpret_cast<const float4*>(g_scale)[lane];
    const float4 bc = reinterpret_cast<const float4*>(g_scale + 128)[lane];
    const float4 ag = reinterpret_cast<const float4*>(g_scale + 256)[lane];
    const float4 bg = reinterpret_cast<const float4*>(g_scale + 384)[lane];

    for (int t0 = warp * 2; t0 < T; t0 += nw * 2) {
        int t1 = t0 + 1;
        bool h1 = t1 < T;
        int k0 = kx[t0];
        int k1 = h1 ? kx[t1] : k0;

        const __half* A0 = g_A + (size_t)t0 * 256;
        const __half* A1 = g_A + (size_t)t1 * 256;
        float4 c0 = ldh4(A0 + c4), g0 = ldh4(A0 + 128 + c4);
        float4 c1, g1;
        if (h1) { c1 = ldh4(A1 + c4); g1 = ldh4(A1 + 128 + c4); }

        {
            float cnx = c0.x * ac.x + bc.x, cny = c0.y * ac.y + bc.y;
            float cnz = c0.z * ac.z + bc.z, cnw = c0.w * ac.w + bc.w;
            float gnx = g0.x * ag.x + bg.x, gny = g0.y * ag.y + bg.y;
            float gnz = g0.z * ag.z + bg.z, gnw = g0.w * ag.w + bg.w;
            float* dst = g_seg + (size_t)k0 * 128 + c4;
            atomicAdd(dst + 0, cnx * sigf(cnx) * sigf(gnx));
            atomicAdd(dst + 1, cny * sigf(cny) * sigf(gny));
            atomicAdd(dst + 2, cnz * sigf(cnz) * sigf(gnz));
            atomicAdd(dst + 3, cnw * sigf(cnw) * sigf(gnw));
        }
        if (h1) {
            float cnx = c1.x * ac.x + bc.x, cny = c1.y * ac.y + bc.y;
            float cnz = c1.z * ac.z + bc.z, cnw = c1.w * ac.w + bc.w;
            float gnx = g1.x * ag.x + bg.x, gny = g1.y * ag.y + bg.y;
            float gnz = g1.z * ag.z + bg.z, gnw = g1.w * ag.w + bg.w;
            float* dst = g_seg + (size_t)k1 * 128 + c4;
            atomicAdd(dst + 0, cnx * sigf(cnx) * sigf(gnx));
            atomicAdd(dst + 1, cny * sigf(cny) * sigf(gny));
            atomicAdd(dst + 2, cnz * sigf(cnz) * sigf(gnz));
            atomicAdd(dst + 3, cnw * sigf(cnw) * sigf(gnw));
        }
    }
}

// ------------------------------------------------------------------
extern "C" void kernel_launch(void* const* d_in, const int* in_sizes, int n_in,
                              void* d_out, int out_size) {
    const float* vertex = (const float*)d_in[0];
    const float* edge   = (const float*)d_in[1];
    const float* angle  = (const float*)d_in[2];
    const int* kx = (const int*)d_in[4];
    const int* jx = (const int*)d_in[5];
    const int* ix = (const int*)d_in[6];
    const float* w_cs = (const float*)d_in[7];
    const float* w_cd = (const float*)d_in[8];
    const float* w_cb = (const float*)d_in[9];
    const float* w_ca = (const float*)d_in[10];
    const float* w_gs = (const float*)d_in[11];
    const float* w_gd = (const float*)d_in[12];
    const float* w_gb = (const float*)d_in[13];
    const float* w_ga = (const float*)d_in[14];
    const float* bcg = (const float*)d_in[15];
    const float* bcb = (const float*)d_in[16];
    const float* bgg = (const float*)d_in[17];
    const float* bgb = (const float*)d_in[18];
    const float* w_out = (const float*)d_in[19];

    const int N = in_sizes[0] / 128;
    const int E = in_sizes[1] / 128;
    const int T = in_sizes[2] / 64;

    __half *pVsrc, *pVdst, *pEp, *pA;
    float *pSeg, *pWv, *pWeb, *pWan;
    cudaGetSymbolAddress((void**)&pVsrc, g_Vsrc);
    cudaGetSymbolAddress((void**)&pVdst, g_Vdst);
    cudaGetSymbolAddress((void**)&pEp, g_Ep);
    cudaGetSymbolAddress((void**)&pA, g_A);
    cudaGetSymbolAddress((void**)&pSeg, g_seg);
    cudaGetSymbolAddress((void**)&pWv, g_Wv);
    cudaGetSymbolAddress((void**)&pWeb, g_Web);
    cudaGetSymbolAddress((void**)&pWan, g_Wan);

    const size_t smem_bytes = 2 * 128 * 72 * sizeof(__half);  // 36864
    cudaFuncSetAttribute(mma_gemm<128, float>,
                         cudaFuncAttributeMaxDynamicSharedMemorySize, (int)smem_bytes);
    cudaFuncSetAttribute(mma_gemm<128, __half>,
                         cudaFuncAttributeMaxDynamicSharedMemorySize, (int)smem_bytes);
    cudaFuncSetAttribute(mma_gemm<64, __half>,
                         cudaFuncAttributeMaxDynamicSharedMemorySize, (int)smem_bytes);
    cudaFuncSetAttribute(mma_gemm_vertex,
                         cudaFuncAttributeMaxDynamicSharedMemorySize, (int)smem_bytes);

    zero_kernel<<<2048, 256>>>(E);
    pack_weights<<<64, 256>>>(w_cs, w_gs, pWv, 16384);           // rows 0-255
    pack_weights<<<64, 256>>>(w_cd, w_gd, pWv + 32768, 16384);   // rows 256-511
    pack_weights<<<64, 256>>>(w_cb, w_gb, pWeb, 16384);
    pack_weights<<<32, 256>>>(w_ca, w_ga, pWan, 8192);

    const int gN = (N + 127) / 128;
    const int gE = (E + 127) / 128;
    const int gT = (T + 127) / 128;

    // vertex: single launch, 4 output tiles (Vsrc core|gate, Vdst core|gate)
    mma_gemm_vertex<<<dim3(gN, 4), 256, smem_bytes>>>(vertex, pWv, pVsrc, pVdst, N);
    mma_gemm<128, __half><<<dim3(gE, 2), 256, smem_bytes>>>(edge,  pWeb, nullptr, pEp, E, 256);
    mma_gemm<64,  __half><<<dim3(gT, 2), 256, smem_bytes>>>(angle, pWan, nullptr, pA,  T, 256);

    // gather-add + BN stats (in-place over g_A, fp16), x2 unrolled
    pass_fuse<<<1184, 256>>>(kx, jx, ix, T);
    finalize_stats<<<1, 128>>>(bcg, bcb, bgg, bgb, 1.0f / (float)T);

    // activation + segment scatter, x2 unrolled
    pass_scatter<<<1184, 256>>>(kx, T);

    // new_bond = seg @ w_out.T + edge_feat  (fp32 output)
    mma_gemm<128, float><<<dim3(gE, 1), 256, smem_bytes>>>(pSeg, w_out, edge,
                                                           (float*)d_out, E, 128);
}

// round 8
// speedup vs baseline: 1.5950x; 1.0951x over previous
#include <cuda_runtime.h>
#include <cuda_fp16.h>
#include <cstdint>

#define BN_EPS 1e-5f
#define MAXN 100000
#define MAXE 400000
#define MAXT 1000000

// ---- scratch (allocation-free, static device globals) ----
__device__ __half g_Vsrc[(size_t)MAXN * 256];  // [N,256] = [core_src | gate_src]
__device__ __half g_Vdst[(size_t)MAXN * 256];  // [N,256] = [core_dst | gate_dst]
__device__ __half g_Ep  [(size_t)MAXE * 256];  // [E,256] = [core_bond | gate_bond]
__device__ __half g_A   [(size_t)MAXT * 256];  // [T,256] fused core|gate (pre-BN)
__device__ float  g_seg [(size_t)MAXE * 128];  // segment sums (fp32 atomics)
__device__ float  g_stats[512];                // sumC | ssqC | sumG | ssqG
__device__ float  g_scale[512];                // aC | bC | aG | bG
__device__ float  g_Wv [512 * 128];            // [w_core_src; w_gate_src; w_core_dst; w_gate_dst]
__device__ float  g_Web[256 * 128];            // [w_core_bond ; w_gate_bond]
__device__ float  g_Wan[256 * 64];             // [w_core_angle ; w_gate_angle]

// ------------------------------------------------------------------
__global__ void zero_kernel(int E) {
    size_t n4 = (size_t)E * 32;
    size_t i = (size_t)blockIdx.x * blockDim.x + threadIdx.x;
    size_t st = (size_t)gridDim.x * blockDim.x;
    float4 z = make_float4(0.f, 0.f, 0.f, 0.f);
    float4* p = reinterpret_cast<float4*>(g_seg);
    for (size_t k = i; k < n4; k += st) p[k] = z;
    if (i < 512) g_stats[i] = 0.f;
}

// pack [a;b] -> out [2*elems]
__global__ void pack_weights(const float* __restrict__ a, const float* __restrict__ b,
                             float* __restrict__ out, int elems) {
    int i = blockIdx.x * blockDim.x + threadIdx.x;
    if (i < elems) { out[i] = a[i]; out[elems + i] = b[i]; }
}

// ---- fp16 helpers ----
__device__ __forceinline__ float4 ldh4(const __half* p) {
    uint2 u = *reinterpret_cast<const uint2*>(p);
    __half2 h0 = *reinterpret_cast<__half2*>(&u.x);
    __half2 h1 = *reinterpret_cast<__half2*>(&u.y);
    float2 f0 = __half22float2(h0);
    float2 f1 = __half22float2(h1);
    return make_float4(f0.x, f0.y, f1.x, f1.y);
}
__device__ __forceinline__ float4 f4add(float4 a, float4 b) {
    return make_float4(a.x + b.x, a.y + b.y, a.z + b.z, a.w + b.w);
}

// ------------------------------------------------------------------
// fp16 mma.sync GEMM core (m16n8k16, fp32 accum). 128x128 tile.
// Accumulators left in c[][][]; epilogue handled by caller templates.
// ------------------------------------------------------------------
template<int K>
__device__ __forceinline__
void gemm_accum(const float* __restrict__ X, const float* __restrict__ W,
                int M, int row0, int wBase, char* smemc, float c[4][4][4]) {
    constexpr int BK = 64;
    constexpr int KP = 72;
    __half* Xs = reinterpret_cast<__half*>(smemc);
    __half* Ws = Xs + 128 * KP;

    const int tid = threadIdx.x;
    const int lane = tid & 31;
    const int wid = tid >> 5;
    const int warpM = wid >> 2;
    const int warpN = wid & 3;
    const int g = lane >> 2;
    const int qc = lane & 3;

#pragma unroll
    for (int mf = 0; mf < 4; ++mf)
#pragma unroll
        for (int nf = 0; nf < 4; ++nf)
#pragma unroll
            for (int q = 0; q < 4; ++q) c[mf][nf][q] = 0.f;

    for (int kt = 0; kt < K; kt += BK) {
        for (int i = tid; i < 128 * (BK / 4); i += 256) {
            int r = i >> 4;
            int k4 = (i & 15) << 2;
            int gr = row0 + r;
            float4 v = make_float4(0.f, 0.f, 0.f, 0.f);
            if (gr < M) v = *reinterpret_cast<const float4*>(X + (size_t)gr * K + kt + k4);
            __half2 h0 = __floats2half2_rn(v.x, v.y);
            __half2 h1 = __floats2half2_rn(v.z, v.w);
            uint2 u = make_uint2(*reinterpret_cast<uint32_t*>(&h0),
                                 *reinterpret_cast<uint32_t*>(&h1));
            *reinterpret_cast<uint2*>(Xs + r * KP + k4) = u;
        }
        for (int i = tid; i < 128 * (BK / 4); i += 256) {
            int r = i >> 4;
            int k4 = (i & 15) << 2;
            float4 v = *reinterpret_cast<const float4*>(W + (size_t)(wBase + r) * K + kt + k4);
            __half2 h0 = __floats2half2_rn(v.x, v.y);
            __half2 h1 = __floats2half2_rn(v.z, v.w);
            uint2 u = make_uint2(*reinterpret_cast<uint32_t*>(&h0),
                                 *reinterpret_cast<uint32_t*>(&h1));
            *reinterpret_cast<uint2*>(Ws + r * KP + k4) = u;
        }
        __syncthreads();

        const uint32_t* Xu = reinterpret_cast<const uint32_t*>(Xs);
        const uint32_t* Wu = reinterpret_cast<const uint32_t*>(Ws);
#pragma unroll
        for (int k0 = 0; k0 < BK; k0 += 16) {
            const int kw = k0 >> 1;
            uint32_t a[4][4], b[4][2];
#pragma unroll
            for (int mf = 0; mf < 4; ++mf) {
                int r = warpM * 64 + mf * 16 + g;
                a[mf][0] = Xu[r * 36 + kw + qc];
                a[mf][1] = Xu[(r + 8) * 36 + kw + qc];
                a[mf][2] = Xu[r * 36 + kw + 4 + qc];
                a[mf][3] = Xu[(r + 8) * 36 + kw + 4 + qc];
            }
#pragma unroll
            for (int nf = 0; nf < 4; ++nf) {
                int n = warpN * 32 + nf * 8 + g;
                b[nf][0] = Wu[n * 36 + kw + qc];
                b[nf][1] = Wu[n * 36 + kw + 4 + qc];
            }
#pragma unroll
            for (int mf = 0; mf < 4; ++mf)
#pragma unroll
                for (int nf = 0; nf < 4; ++nf) {
                    asm volatile(
                        "mma.sync.aligned.m16n8k16.row.col.f32.f16.f16.f32 "
                        "{%0,%1,%2,%3}, {%4,%5,%6,%7}, {%8,%9}, {%0,%1,%2,%3};"
                        : "+f"(c[mf][nf][0]), "+f"(c[mf][nf][1]),
                          "+f"(c[mf][nf][2]), "+f"(c[mf][nf][3])
                        : "r"(a[mf][0]), "r"(a[mf][1]), "r"(a[mf][2]), "r"(a[mf][3]),
                          "r"(b[nf][0]), "r"(b[nf][1]));
                }
        }
        __syncthreads();
    }
}

template<int K, typename OutT>
__global__ __launch_bounds__(256, 2)
void mma_gemm(const float* __restrict__ X, const float* __restrict__ W,
              const float* __restrict__ Dadd, OutT* __restrict__ C,
              int M, int ldc) {
    extern __shared__ char smemc[];
    float c[4][4][4];
    const int row0 = blockIdx.x * 128;
    const int nBase = blockIdx.y * 128;
    gemm_accum<K>(X, W, M, row0, nBase, smemc, c);

    const int lane = threadIdx.x & 31;
    const int wid = threadIdx.x >> 5;
    const int warpM = wid >> 2, warpN = wid & 3;
    const int g = lane >> 2, qc = lane & 3;
#pragma unroll
    for (int mf = 0; mf < 4; ++mf) {
#pragma unroll
        for (int nf = 0; nf < 4; ++nf) {
            int col = nBase + warpN * 32 + nf * 8 + qc * 2;
#pragma unroll
            for (int half = 0; half < 2; ++half) {
                int r = row0 + warpM * 64 + mf * 16 + g + half * 8;
                if (r >= M) continue;
                float ox = c[mf][nf][half * 2 + 0];
                float oy = c[mf][nf][half * 2 + 1];
                if constexpr (sizeof(OutT) == 4) {
                    if (Dadd) {
                        float2 d = *reinterpret_cast<const float2*>(
                            Dadd + (size_t)r * ldc + col);
                        ox += d.x; oy += d.y;
                    }
                    *reinterpret_cast<float2*>(
                        reinterpret_cast<float*>(C) + (size_t)r * ldc + col) =
                        make_float2(ox, oy);
                } else {
                    __half2 h = __floats2half2_rn(ox, oy);
                    *reinterpret_cast<__half2*>(
                        reinterpret_cast<__half*>(C) + (size_t)r * ldc + col) = h;
                }
            }
        }
    }
}

// merged vertex GEMM: y in 0..3 -> [Vsrc core, Vsrc gate, Vdst core, Vdst gate]
__global__ __launch_bounds__(256, 2)
void mma_gemm_vertex(const float* __restrict__ X, const float* __restrict__ W,
                     __half* __restrict__ C0, __half* __restrict__ C1, int M) {
    extern __shared__ char smemc[];
    float c[4][4][4];
    const int y = blockIdx.y;
    const int row0 = blockIdx.x * 128;
    __half* C = (y < 2) ? C0 : C1;
    const int colBase = (y & 1) * 128;
    gemm_accum<128>(X, W, M, row0, y * 128, smemc, c);

    const int lane = threadIdx.x & 31;
    const int wid = threadIdx.x >> 5;
    const int warpM = wid >> 2, warpN = wid & 3;
    const int g = lane >> 2, qc = lane & 3;
#pragma unroll
    for (int mf = 0; mf < 4; ++mf) {
#pragma unroll
        for (int nf = 0; nf < 4; ++nf) {
            int col = colBase + warpN * 32 + nf * 8 + qc * 2;
#pragma unroll
            for (int half = 0; half < 2; ++half) {
                int r = row0 + warpM * 64 + mf * 16 + g + half * 8;
                if (r >= M) continue;
                __half2 h = __floats2half2_rn(c[mf][nf][half * 2 + 0],
                                              c[mf][nf][half * 2 + 1]);
                *reinterpret_cast<__half2*>(C + (size_t)r * 256 + col) = h;
            }
        }
    }
}

// ------------------------------------------------------------------
// Fused angle GEMM (K=64) + gather-add + BN stats.
// grid (ceil(T/128), 2): y=0 -> core half, y=1 -> gate half.
// Phase 1: MMA into fragments. Phase 2: stage tile to smem (fp16).
// Phase 3: warp-per-row coalesced gathers of Vsrc/Ep/Vdst, add, store g_A,
//          accumulate per-column stats regs -> smem -> global.
// ------------------------------------------------------------------
__global__ __launch_bounds__(256, 2)
void angle_fuse(const float* __restrict__ X, const float* __restrict__ W,
                const int* __restrict__ kx, const int* __restrict__ jx,
                const int* __restrict__ ix, int T) {
    extern __shared__ char smemc[];
    __shared__ float s_sum[128];
    __shared__ float s_ssq[128];

    const int tid = threadIdx.x;
    const int lane = tid & 31;
    const int wid = tid >> 5;
    const int warpM = wid >> 2, warpN = wid & 3;
    const int g = lane >> 2, qc = lane & 3;
    const int row0 = blockIdx.x * 128;
    const int y = blockIdx.y;
    const int nBase = y * 128;

    if (tid < 128) { s_sum[tid] = 0.f; s_ssq[tid] = 0.f; }

    float c[4][4][4];
    gemm_accum<64>(X, W, T, row0, nBase, smemc, c);
    // gemm_accum ends with __syncthreads(): smem is free to reuse.

    // ---- phase 2: stage C tile to smem, stride 136 halves ----
    __half* Cs = reinterpret_cast<__half*>(smemc);
#pragma unroll
    for (int mf = 0; mf < 4; ++mf) {
#pragma unroll
        for (int nf = 0; nf < 4; ++nf) {
            int col = warpN * 32 + nf * 8 + qc * 2;
#pragma unroll
            for (int half = 0; half < 2; ++half) {
                int r = warpM * 64 + mf * 16 + g + half * 8;
                __half2 h = __floats2half2_rn(c[mf][nf][half * 2 + 0],
                                              c[mf][nf][half * 2 + 1]);
                *reinterpret_cast<__half2*>(Cs + r * 136 + col) = h;
            }
        }
    }
    __syncthreads();

    // ---- phase 3: warp-per-row gather-add ----
    const int c4 = lane * 4;
    float4 sum = make_float4(0, 0, 0, 0), ssq = make_float4(0, 0, 0, 0);

    for (int rr = 0; rr < 16; rr += 2) {
        int r0 = wid * 16 + rr;
        int t0 = row0 + r0;
        int t1 = t0 + 1;
        bool v0 = t0 < T, v1 = t1 < T;

        float4 a0, s0, e0, d0, a1, s1, e1, d1;
        if (v0) {
            int j = jx[t0], k = kx[t0], i = ix[t0];
            a0 = ldh4(Cs + r0 * 136 + c4);
            s0 = ldh4(g_Vsrc + (size_t)j * 256 + nBase + c4);
            e0 = ldh4(g_Ep   + (size_t)k * 256 + nBase + c4);
            d0 = ldh4(g_Vdst + (size_t)i * 256 + nBase + c4);
        }
        if (v1) {
            int j = jx[t1], k = kx[t1], i = ix[t1];
            a1 = ldh4(Cs + (r0 + 1) * 136 + c4);
            s1 = ldh4(g_Vsrc + (size_t)j * 256 + nBase + c4);
            e1 = ldh4(g_Ep   + (size_t)k * 256 + nBase + c4);
            d1 = ldh4(g_Vdst + (size_t)i * 256 + nBase + c4);
        }

        if (v0) {
            float4 o = f4add(f4add(a0, s0), f4add(e0, d0));
            __half2 h0 = __floats2half2_rn(o.x, o.y);
            __half2 h1 = __floats2half2_rn(o.z, o.w);
            uint2 u = make_uint2(*reinterpret_cast<uint32_t*>(&h0),
                                 *reinterpret_cast<uint32_t*>(&h1));
            *reinterpret_cast<uint2*>(g_A + (size_t)t0 * 256 + nBase + c4) = u;
            float2 f0 = __half22float2(h0), f1 = __half22float2(h1);
            sum.x += f0.x; sum.y += f0.y; sum.z += f1.x; sum.w += f1.y;
            ssq.x += f0.x * f0.x; ssq.y += f0.y * f0.y;
            ssq.z += f1.x * f1.x; ssq.w += f1.y * f1.y;
        }
        if (v1) {
            float4 o = f4add(f4add(a1, s1), f4add(e1, d1));
            __half2 h0 = __floats2half2_rn(o.x, o.y);
            __half2 h1 = __floats2half2_rn(o.z, o.w);
            uint2 u = make_uint2(*reinterpret_cast<uint32_t*>(&h0),
                                 *reinterpret_cast<uint32_t*>(&h1));
            *reinterpret_cast<uint2*>(g_A + (size_t)t1 * 256 + nBase + c4) = u;
            float2 f0 = __half22float2(h0), f1 = __half22float2(h1);
            sum.x += f0.x; sum.y += f0.y; sum.z += f1.x; sum.w += f1.y;
            ssq.x += f0.x * f0.x; ssq.y += f0.y * f0.y;
            ssq.z += f1.x * f1.x; ssq.w += f1.y * f1.y;
        }
    }

    // regs -> smem (spread-address atomics) -> global (128 threads, 2 each)
    atomicAdd(&s_sum[c4 + 0], sum.x); atomicAdd(&s_sum[c4 + 1], sum.y);
    atomicAdd(&s_sum[c4 + 2], sum.z); atomicAdd(&s_sum[c4 + 3], sum.w);
    atomicAdd(&s_ssq[c4 + 0], ssq.x); atomicAdd(&s_ssq[c4 + 1], ssq.y);
    atomicAdd(&s_ssq[c4 + 2], ssq.z); atomicAdd(&s_ssq[c4 + 3], ssq.w);
    __syncthreads();
    if (tid < 128) {
        atomicAdd(&g_stats[y * 256 + tid], s_sum[tid]);
        atomicAdd(&g_stats[y * 256 + 128 + tid], s_ssq[tid]);
    }
}

// ------------------------------------------------------------------
__global__ void finalize_stats(const float* __restrict__ gamC, const float* __restrict__ betC,
                               const float* __restrict__ gamG, const float* __restrict__ betG,
                               float invT) {
    int c = threadIdx.x;  // 128 threads
    float m = g_stats[c] * invT;
    float v = g_stats[128 + c] * invT - m * m;
    float a = rsqrtf(v + BN_EPS) * gamC[c];
    g_scale[c] = a;
    g_scale[128 + c] = betC[c] - m * a;

    m = g_stats[256 + c] * invT;
    v = g_stats[384 + c] * invT - m * m;
    a = rsqrtf(v + BN_EPS) * gamG[c];
    g_scale[256 + c] = a;
    g_scale[384 + c] = betG[c] - m * a;
}

// ------------------------------------------------------------------
__device__ __forceinline__ float sigf(float x) { return 1.0f / (1.0f + __expf(-x)); }

__global__ void pass_scatter(const int* __restrict__ kx, int T) {
    const int lane = threadIdx.x & 31;
    int warp = (blockIdx.x * blockDim.x + threadIdx.x) >> 5;
    const int nw = (gridDim.x * blockDim.x) >> 5;
    const int c4 = lane * 4;

    const float4 ac = reinterpret_cast<const float4*>(g_scale)[lane];
    const float4 bc = reinterpret_cast<const float4*>(g_scale + 128)[lane];
    const float4 ag = reinterpret_cast<const float4*>(g_scale + 256)[lane];
    const float4 bg = reinterpret_cast<const float4*>(g_scale + 384)[lane];

    for (int t0 = warp * 2; t0 < T; t0 += nw * 2) {
        int t1 = t0 + 1;
        bool h1 = t1 < T;
        int k0 = kx[t0];
        int k1 = h1 ? kx[t1] : k0;

        const __half* A0 = g_A + (size_t)t0 * 256;
        const __half* A1 = g_A + (size_t)t1 * 256;
        float4 c0 = ldh4(A0 + c4), g0 = ldh4(A0 + 128 + c4);
        float4 c1, g1;
        if (h1) { c1 = ldh4(A1 + c4); g1 = ldh4(A1 + 128 + c4); }

        {
            float cnx = c0.x * ac.x + bc.x, cny = c0.y * ac.y + bc.y;
            float cnz = c0.z * ac.z + bc.z, cnw = c0.w * ac.w + bc.w;
            float gnx = g0.x * ag.x + bg.x, gny = g0.y * ag.y + bg.y;
            float gnz = g0.z * ag.z + bg.z, gnw = g0.w * ag.w + bg.w;
            float* dst = g_seg + (size_t)k0 * 128 + c4;
            atomicAdd(dst + 0, cnx * sigf(cnx) * sigf(gnx));
            atomicAdd(dst + 1, cny * sigf(cny) * sigf(gny));
            atomicAdd(dst + 2, cnz * sigf(cnz) * sigf(gnz));
            atomicAdd(dst + 3, cnw * sigf(cnw) * sigf(gnw));
        }
        if (h1) {
            float cnx = c1.x * ac.x + bc.x, cny = c1.y * ac.y + bc.y;
            float cnz = c1.z * ac.z + bc.z, cnw = c1.w * ac.w + bc.w;
            float gnx = g1.x * ag.x + bg.x, gny = g1.y * ag.y + bg.y;
            float gnz = g1.z * ag.z + bg.z, gnw = g1.w * ag.w + bg.w;
            float* dst = g_seg + (size_t)k1 * 128 + c4;
            atomicAdd(dst + 0, cnx * sigf(cnx) * sigf(gnx));
            atomicAdd(dst + 1, cny * sigf(cny) * sigf(gny));
            atomicAdd(dst + 2, cnz * sigf(cnz) * sigf(gnz));
            atomicAdd(dst + 3, cnw * sigf(cnw) * sigf(gnw));
        }
    }
}

// ------------------------------------------------------------------
extern "C" void kernel_launch(void* const* d_in, const int* in_sizes, int n_in,
                              void* d_out, int out_size) {
    const float* vertex = (const float*)d_in[0];
    const float* edge   = (const float*)d_in[1];
    const float* angle  = (const float*)d_in[2];
    const int* kx = (const int*)d_in[4];
    const int* jx = (const int*)d_in[5];
    const int* ix = (const int*)d_in[6];
    const float* w_cs = (const float*)d_in[7];
    const float* w_cd = (const float*)d_in[8];
    const float* w_cb = (const float*)d_in[9];
    const float* w_ca = (const float*)d_in[10];
    const float* w_gs = (const float*)d_in[11];
    const float* w_gd = (const float*)d_in[12];
    const float* w_gb = (const float*)d_in[13];
    const float* w_ga = (const float*)d_in[14];
    const float* bcg = (const float*)d_in[15];
    const float* bcb = (const float*)d_in[16];
    const float* bgg = (const float*)d_in[17];
    const float* bgb = (const float*)d_in[18];
    const float* w_out = (const float*)d_in[19];

    const int N = in_sizes[0] / 128;
    const int E = in_sizes[1] / 128;
    const int T = in_sizes[2] / 64;

    __half *pVsrc, *pVdst, *pEp;
    float *pSeg, *pWv, *pWeb, *pWan;
    cudaGetSymbolAddress((void**)&pVsrc, g_Vsrc);
    cudaGetSymbolAddress((void**)&pVdst, g_Vdst);
    cudaGetSymbolAddress((void**)&pEp, g_Ep);
    cudaGetSymbolAddress((void**)&pSeg, g_seg);
    cudaGetSymbolAddress((void**)&pWv, g_Wv);
    cudaGetSymbolAddress((void**)&pWeb, g_Web);
    cudaGetSymbolAddress((void**)&pWan, g_Wan);

    const size_t smem_bytes = 2 * 128 * 72 * sizeof(__half);  // 36864
    cudaFuncSetAttribute(mma_gemm<128, float>,
                         cudaFuncAttributeMaxDynamicSharedMemorySize, (int)smem_bytes);
    cudaFuncSetAttribute(mma_gemm<128, __half>,
                         cudaFuncAttributeMaxDynamicSharedMemorySize, (int)smem_bytes);
    cudaFuncSetAttribute(mma_gemm_vertex,
                         cudaFuncAttributeMaxDynamicSharedMemorySize, (int)smem_bytes);
    cudaFuncSetAttribute(angle_fuse,
                         cudaFuncAttributeMaxDynamicSharedMemorySize, (int)smem_bytes);

    zero_kernel<<<2048, 256>>>(E);
    pack_weights<<<64, 256>>>(w_cs, w_gs, pWv, 16384);           // rows 0-255
    pack_weights<<<64, 256>>>(w_cd, w_gd, pWv + 32768, 16384);   // rows 256-511
    pack_weights<<<64, 256>>>(w_cb, w_gb, pWeb, 16384);
    pack_weights<<<32, 256>>>(w_ca, w_ga, pWan, 8192);

    const int gN = (N + 127) / 128;
    const int gE = (E + 127) / 128;
    const int gT = (T + 127) / 128;

    // vertex: single launch, 4 output tiles (Vsrc core|gate, Vdst core|gate)
    mma_gemm_vertex<<<dim3(gN, 4), 256, smem_bytes>>>(vertex, pWv, pVsrc, pVdst, N);
    mma_gemm<128, __half><<<dim3(gE, 2), 256, smem_bytes>>>(edge, pWeb, nullptr, pEp, E, 256);

    // fused: angle GEMM + gather-add + BN stats (writes g_A exactly once)
    angle_fuse<<<dim3(gT, 2), 256, smem_bytes>>>(angle, pWan, kx, jx, ix, T);

    finalize_stats<<<1, 128>>>(bcg, bcb, bgg, bgb, 1.0f / (float)T);

    // activation + segment scatter, x2 unrolled
    pass_scatter<<<1184, 256>>>(kx, T);

    // new_bond = seg @ w_out.T + edge_feat  (fp32 output)
    mma_gemm<128, float><<<dim3(gE, 1), 256, smem_bytes>>>(pSeg, w_out, edge,
                                                           (float*)d_out, E, 128);
}

// round 9
// speedup vs baseline: 2.2068x; 1.3835x over previous
#include <cuda_runtime.h>
#include <cuda_fp16.h>
#include <cstdint>

#define BN_EPS 1e-5f
#define MAXN 100000
#define MAXE 400000
#define MAXT 1000000

// ---- scratch (allocation-free, static device globals) ----
__device__ __half g_Vsrc[(size_t)MAXN * 256];  // [N,256] = [core_src | gate_src]
__device__ __half g_Vdst[(size_t)MAXN * 256];  // [N,256] = [core_dst | gate_dst]
__device__ __half g_Ep  [(size_t)MAXE * 256];  // [E,256] = [core_bond | gate_bond]
__device__ __half g_A   [(size_t)MAXT * 256];  // [T,256] fused core|gate (pre-BN)
__device__ __half g_seg [(size_t)MAXE * 128];  // segment sums (fp16x2 atomics)
__device__ float  g_stats[512];                // sumC | ssqC | sumG | ssqG
__device__ float  g_scale[512];                // aC | bC | aG | bG
__device__ float  g_Wv [512 * 128];            // [w_core_src; w_gate_src; w_core_dst; w_gate_dst]
__device__ float  g_Web[256 * 128];            // [w_core_bond ; w_gate_bond]
__device__ float  g_Wan[256 * 64];             // [w_core_angle ; w_gate_angle]

// ------------------------------------------------------------------
__global__ void zero_kernel(int E) {
    size_t n16 = (size_t)E * 16;   // E*128 halves = E*256 bytes / 16
    size_t i = (size_t)blockIdx.x * blockDim.x + threadIdx.x;
    size_t st = (size_t)gridDim.x * blockDim.x;
    uint4 z = make_uint4(0, 0, 0, 0);
    uint4* p = reinterpret_cast<uint4*>(g_seg);
    for (size_t k = i; k < n16; k += st) p[k] = z;
    if (i < 512) g_stats[i] = 0.f;
}

// pack [a;b] -> out [2*elems]
__global__ void pack_weights(const float* __restrict__ a, const float* __restrict__ b,
                             float* __restrict__ out, int elems) {
    int i = blockIdx.x * blockDim.x + threadIdx.x;
    if (i < elems) { out[i] = a[i]; out[elems + i] = b[i]; }
}

// ---- fp16 helpers ----
__device__ __forceinline__ float4 ldh4(const __half* p) {
    uint2 u = *reinterpret_cast<const uint2*>(p);
    __half2 h0 = *reinterpret_cast<__half2*>(&u.x);
    __half2 h1 = *reinterpret_cast<__half2*>(&u.y);
    float2 f0 = __half22float2(h0);
    float2 f1 = __half22float2(h1);
    return make_float4(f0.x, f0.y, f1.x, f1.y);
}
__device__ __forceinline__ float4 f4add(float4 a, float4 b) {
    return make_float4(a.x + b.x, a.y + b.y, a.z + b.z, a.w + b.w);
}

// ------------------------------------------------------------------
// inner 128x128x64 fp16 MMA sweep over staged smem tiles (stride 36 words)
// ------------------------------------------------------------------
__device__ __forceinline__
void mma64(const __half* Xs, const __half* Ws, float c[4][4][4],
           int warpM, int warpN, int g, int qc) {
    const uint32_t* Xu = reinterpret_cast<const uint32_t*>(Xs);
    const uint32_t* Wu = reinterpret_cast<const uint32_t*>(Ws);
#pragma unroll
    for (int k0 = 0; k0 < 64; k0 += 16) {
        const int kw = k0 >> 1;
        uint32_t a[4][4], b[4][2];
#pragma unroll
        for (int mf = 0; mf < 4; ++mf) {
            int r = warpM * 64 + mf * 16 + g;
            a[mf][0] = Xu[r * 36 + kw + qc];
            a[mf][1] = Xu[(r + 8) * 36 + kw + qc];
            a[mf][2] = Xu[r * 36 + kw + 4 + qc];
            a[mf][3] = Xu[(r + 8) * 36 + kw + 4 + qc];
        }
#pragma unroll
        for (int nf = 0; nf < 4; ++nf) {
            int n = warpN * 32 + nf * 8 + g;
            b[nf][0] = Wu[n * 36 + kw + qc];
            b[nf][1] = Wu[n * 36 + kw + 4 + qc];
        }
#pragma unroll
        for (int mf = 0; mf < 4; ++mf)
#pragma unroll
            for (int nf = 0; nf < 4; ++nf) {
                asm volatile(
                    "mma.sync.aligned.m16n8k16.row.col.f32.f16.f16.f32 "
                    "{%0,%1,%2,%3}, {%4,%5,%6,%7}, {%8,%9}, {%0,%1,%2,%3};"
                    : "+f"(c[mf][nf][0]), "+f"(c[mf][nf][1]),
                      "+f"(c[mf][nf][2]), "+f"(c[mf][nf][3])
                    : "r"(a[mf][0]), "r"(a[mf][1]), "r"(a[mf][2]), "r"(a[mf][3]),
                      "r"(b[nf][0]), "r"(b[nf][1]));
            }
    }
}

// ------------------------------------------------------------------
// generic GEMM accumulate (input fp32 or fp16), 128x128 tile
// ------------------------------------------------------------------
template<int K, typename InT>
__device__ __forceinline__
void gemm_accum(const InT* __restrict__ X, const float* __restrict__ W,
                int M, int row0, int wBase, char* smemc, float c[4][4][4]) {
    constexpr int BK = 64;
    constexpr int KP = 72;
    __half* Xs = reinterpret_cast<__half*>(smemc);
    __half* Ws = Xs + 128 * KP;

    const int tid = threadIdx.x;
    const int lane = tid & 31;
    const int wid = tid >> 5;
    const int warpM = wid >> 2, warpN = wid & 3;
    const int g = lane >> 2, qc = lane & 3;

#pragma unroll
    for (int mf = 0; mf < 4; ++mf)
#pragma unroll
        for (int nf = 0; nf < 4; ++nf)
#pragma unroll
            for (int q = 0; q < 4; ++q) c[mf][nf][q] = 0.f;

    for (int kt = 0; kt < K; kt += BK) {
        for (int i = tid; i < 128 * (BK / 4); i += 256) {
            int r = i >> 4;
            int k4 = (i & 15) << 2;
            int gr = row0 + r;
            if constexpr (sizeof(InT) == 4) {
                float4 v = make_float4(0.f, 0.f, 0.f, 0.f);
                if (gr < M)
                    v = *reinterpret_cast<const float4*>(X + (size_t)gr * K + kt + k4);
                __half2 h0 = __floats2half2_rn(v.x, v.y);
                __half2 h1 = __floats2half2_rn(v.z, v.w);
                uint2 u = make_uint2(*reinterpret_cast<uint32_t*>(&h0),
                                     *reinterpret_cast<uint32_t*>(&h1));
                *reinterpret_cast<uint2*>(Xs + r * KP + k4) = u;
            } else {
                uint2 u = make_uint2(0u, 0u);
                if (gr < M)
                    u = *reinterpret_cast<const uint2*>(X + (size_t)gr * K + kt + k4);
                *reinterpret_cast<uint2*>(Xs + r * KP + k4) = u;
            }
        }
        for (int i = tid; i < 128 * (BK / 4); i += 256) {
            int r = i >> 4;
            int k4 = (i & 15) << 2;
            float4 v = *reinterpret_cast<const float4*>(W + (size_t)(wBase + r) * K + kt + k4);
            __half2 h0 = __floats2half2_rn(v.x, v.y);
            __half2 h1 = __floats2half2_rn(v.z, v.w);
            uint2 u = make_uint2(*reinterpret_cast<uint32_t*>(&h0),
                                 *reinterpret_cast<uint32_t*>(&h1));
            *reinterpret_cast<uint2*>(Ws + r * KP + k4) = u;
        }
        __syncthreads();
        mma64(Xs, Ws, c, warpM, warpN, g, qc);
        __syncthreads();
    }
}

template<int K, typename InT, typename OutT>
__global__ __launch_bounds__(256, 2)
void mma_gemm(const InT* __restrict__ X, const float* __restrict__ W,
              const float* __restrict__ Dadd, OutT* __restrict__ C,
              int M, int ldc) {
    extern __shared__ char smemc[];
    float c[4][4][4];
    const int row0 = blockIdx.x * 128;
    const int nBase = blockIdx.y * 128;
    gemm_accum<K, InT>(X, W, M, row0, nBase, smemc, c);

    const int lane = threadIdx.x & 31;
    const int wid = threadIdx.x >> 5;
    const int warpM = wid >> 2, warpN = wid & 3;
    const int g = lane >> 2, qc = lane & 3;
#pragma unroll
    for (int mf = 0; mf < 4; ++mf) {
#pragma unroll
        for (int nf = 0; nf < 4; ++nf) {
            int col = nBase + warpN * 32 + nf * 8 + qc * 2;
#pragma unroll
            for (int half = 0; half < 2; ++half) {
                int r = row0 + warpM * 64 + mf * 16 + g + half * 8;
                if (r >= M) continue;
                float ox = c[mf][nf][half * 2 + 0];
                float oy = c[mf][nf][half * 2 + 1];
                if constexpr (sizeof(OutT) == 4) {
                    if (Dadd) {
                        float2 d = *reinterpret_cast<const float2*>(
                            Dadd + (size_t)r * ldc + col);
                        ox += d.x; oy += d.y;
                    }
                    *reinterpret_cast<float2*>(
                        reinterpret_cast<float*>(C) + (size_t)r * ldc + col) =
                        make_float2(ox, oy);
                } else {
                    __half2 h = __floats2half2_rn(ox, oy);
                    *reinterpret_cast<__half2*>(
                        reinterpret_cast<__half*>(C) + (size_t)r * ldc + col) = h;
                }
            }
        }
    }
}

// merged vertex GEMM: y in 0..3 -> [Vsrc core, Vsrc gate, Vdst core, Vdst gate]
__global__ __launch_bounds__(256, 2)
void mma_gemm_vertex(const float* __restrict__ X, const float* __restrict__ W,
                     __half* __restrict__ C0, __half* __restrict__ C1, int M) {
    extern __shared__ char smemc[];
    float c[4][4][4];
    const int y = blockIdx.y;
    const int row0 = blockIdx.x * 128;
    __half* C = (y < 2) ? C0 : C1;
    const int colBase = (y & 1) * 128;
    gemm_accum<128, float>(X, W, M, row0, y * 128, smemc, c);

    const int lane = threadIdx.x & 31;
    const int wid = threadIdx.x >> 5;
    const int warpM = wid >> 2, warpN = wid & 3;
    const int g = lane >> 2, qc = lane & 3;
#pragma unroll
    for (int mf = 0; mf < 4; ++mf) {
#pragma unroll
        for (int nf = 0; nf < 4; ++nf) {
            int col = colBase + warpN * 32 + nf * 8 + qc * 2;
#pragma unroll
            for (int half = 0; half < 2; ++half) {
                int r = row0 + warpM * 64 + mf * 16 + g + half * 8;
                if (r >= M) continue;
                __half2 h = __floats2half2_rn(c[mf][nf][half * 2 + 0],
                                              c[mf][nf][half * 2 + 1]);
                *reinterpret_cast<__half2*>(C + (size_t)r * 256 + col) = h;
            }
        }
    }
}

// ------------------------------------------------------------------
// Fused angle GEMM over FULL N=256 + gather-add + BN stats.
// One block covers 128 t-rows x 256 cols. Xs loaded once; two MMA passes
// (core / gate W rows) share it. Staged tile 128x264 fp16 in smem, then
// warp-per-row gathers with each index loaded exactly once.
// smem: Xs 18432 + Ws 18432 + Cs 67584 = 104448 B  (2 CTA/SM)
// ------------------------------------------------------------------
__global__ __launch_bounds__(256, 2)
void angle_fuse(const float* __restrict__ X, const float* __restrict__ W,
                const int* __restrict__ kx, const int* __restrict__ jx,
                const int* __restrict__ ix, int T) {
    extern __shared__ char smemc[];
    __half* Xs = reinterpret_cast<__half*>(smemc);       // [128][72]
    __half* Ws = Xs + 128 * 72;                          // [128][72]
    __half* Cs = Ws + 128 * 72;                          // [128][264]
    __shared__ float s_sum[256];
    __shared__ float s_ssq[256];

    const int tid = threadIdx.x;
    const int lane = tid & 31;
    const int wid = tid >> 5;
    const int warpM = wid >> 2, warpN = wid & 3;
    const int g = lane >> 2, qc = lane & 3;
    const int row0 = blockIdx.x * 128;

    s_sum[tid] = 0.f; s_ssq[tid] = 0.f;

    // ---- load Xs (K=64, single tile) ----
    for (int i = tid; i < 128 * 16; i += 256) {
        int r = i >> 4;
        int k4 = (i & 15) << 2;
        int gr = row0 + r;
        float4 v = make_float4(0.f, 0.f, 0.f, 0.f);
        if (gr < T) v = *reinterpret_cast<const float4*>(X + (size_t)gr * 64 + k4);
        __half2 h0 = __floats2half2_rn(v.x, v.y);
        __half2 h1 = __floats2half2_rn(v.z, v.w);
        uint2 u = make_uint2(*reinterpret_cast<uint32_t*>(&h0),
                             *reinterpret_cast<uint32_t*>(&h1));
        *reinterpret_cast<uint2*>(Xs + r * 72 + k4) = u;
    }

    float c[4][4][4];

#pragma unroll
    for (int pass = 0; pass < 2; ++pass) {
        // load Ws: rows pass*128 .. +127
        for (int i = tid; i < 128 * 16; i += 256) {
            int r = i >> 4;
            int k4 = (i & 15) << 2;
            float4 v = *reinterpret_cast<const float4*>(
                W + (size_t)(pass * 128 + r) * 64 + k4);
            __half2 h0 = __floats2half2_rn(v.x, v.y);
            __half2 h1 = __floats2half2_rn(v.z, v.w);
            uint2 u = make_uint2(*reinterpret_cast<uint32_t*>(&h0),
                                 *reinterpret_cast<uint32_t*>(&h1));
            *reinterpret_cast<uint2*>(Ws + r * 72 + k4) = u;
        }
        __syncthreads();

#pragma unroll
        for (int mf = 0; mf < 4; ++mf)
#pragma unroll
            for (int nf = 0; nf < 4; ++nf)
#pragma unroll
                for (int q = 0; q < 4; ++q) c[mf][nf][q] = 0.f;
        mma64(Xs, Ws, c, warpM, warpN, g, qc);

        // stage to Cs columns [pass*128, pass*128+128)
#pragma unroll
        for (int mf = 0; mf < 4; ++mf) {
#pragma unroll
            for (int nf = 0; nf < 4; ++nf) {
                int col = pass * 128 + warpN * 32 + nf * 8 + qc * 2;
#pragma unroll
                for (int half = 0; half < 2; ++half) {
                    int r = warpM * 64 + mf * 16 + g + half * 8;
                    __half2 h = __floats2half2_rn(c[mf][nf][half * 2 + 0],
                                                  c[mf][nf][half * 2 + 1]);
                    *reinterpret_cast<__half2*>(Cs + r * 264 + col) = h;
                }
            }
        }
        __syncthreads();   // Ws free for next pass / Cs complete for phase 3
    }

    // ---- phase 3: warp-per-row gather-add over full 256 cols ----
    const int c4 = lane * 4;
    float4 sumC = make_float4(0, 0, 0, 0), ssqC = make_float4(0, 0, 0, 0);
    float4 sumG = make_float4(0, 0, 0, 0), ssqG = make_float4(0, 0, 0, 0);

    for (int rr = 0; rr < 16; rr += 2) {
        int r0 = wid * 16 + rr;
        int t0 = row0 + r0;
        int t1 = t0 + 1;
        bool v0 = t0 < T, v1 = t1 < T;

        float4 aC0, aG0, sC0, sG0, eC0, eG0, dC0, dG0;
        float4 aC1, aG1, sC1, sG1, eC1, eG1, dC1, dG1;
        if (v0) {
            int j = jx[t0], k = kx[t0], i = ix[t0];
            aC0 = ldh4(Cs + r0 * 264 + c4);
            aG0 = ldh4(Cs + r0 * 264 + 128 + c4);
            sC0 = ldh4(g_Vsrc + (size_t)j * 256 + c4);
            sG0 = ldh4(g_Vsrc + (size_t)j * 256 + 128 + c4);
            eC0 = ldh4(g_Ep + (size_t)k * 256 + c4);
            eG0 = ldh4(g_Ep + (size_t)k * 256 + 128 + c4);
            dC0 = ldh4(g_Vdst + (size_t)i * 256 + c4);
            dG0 = ldh4(g_Vdst + (size_t)i * 256 + 128 + c4);
        }
        if (v1) {
            int j = jx[t1], k = kx[t1], i = ix[t1];
            aC1 = ldh4(Cs + (r0 + 1) * 264 + c4);
            aG1 = ldh4(Cs + (r0 + 1) * 264 + 128 + c4);
            sC1 = ldh4(g_Vsrc + (size_t)j * 256 + c4);
            sG1 = ldh4(g_Vsrc + (size_t)j * 256 + 128 + c4);
            eC1 = ldh4(g_Ep + (size_t)k * 256 + c4);
            eG1 = ldh4(g_Ep + (size_t)k * 256 + 128 + c4);
            dC1 = ldh4(g_Vdst + (size_t)i * 256 + c4);
            dG1 = ldh4(g_Vdst + (size_t)i * 256 + 128 + c4);
        }

#pragma unroll
        for (int u = 0; u < 2; ++u) {
            bool v = u ? v1 : v0;
            if (!v) continue;
            int t = u ? t1 : t0;
            float4 oc = u ? f4add(f4add(aC1, sC1), f4add(eC1, dC1))
                          : f4add(f4add(aC0, sC0), f4add(eC0, dC0));
            float4 og = u ? f4add(f4add(aG1, sG1), f4add(eG1, dG1))
                          : f4add(f4add(aG0, sG0), f4add(eG0, dG0));
            __half2 hc0 = __floats2half2_rn(oc.x, oc.y);
            __half2 hc1 = __floats2half2_rn(oc.z, oc.w);
            __half2 hg0 = __floats2half2_rn(og.x, og.y);
            __half2 hg1 = __floats2half2_rn(og.z, og.w);
            uint2 uc = make_uint2(*reinterpret_cast<uint32_t*>(&hc0),
                                  *reinterpret_cast<uint32_t*>(&hc1));
            uint2 ug = make_uint2(*reinterpret_cast<uint32_t*>(&hg0),
                                  *reinterpret_cast<uint32_t*>(&hg1));
            *reinterpret_cast<uint2*>(g_A + (size_t)t * 256 + c4) = uc;
            *reinterpret_cast<uint2*>(g_A + (size_t)t * 256 + 128 + c4) = ug;
            float2 fc0 = __half22float2(hc0), fc1 = __half22float2(hc1);
            float2 fg0 = __half22float2(hg0), fg1 = __half22float2(hg1);
            sumC.x += fc0.x; sumC.y += fc0.y; sumC.z += fc1.x; sumC.w += fc1.y;
            ssqC.x += fc0.x * fc0.x; ssqC.y += fc0.y * fc0.y;
            ssqC.z += fc1.x * fc1.x; ssqC.w += fc1.y * fc1.y;
            sumG.x += fg0.x; sumG.y += fg0.y; sumG.z += fg1.x; sumG.w += fg1.y;
            ssqG.x += fg0.x * fg0.x; ssqG.y += fg0.y * fg0.y;
            ssqG.z += fg1.x * fg1.x; ssqG.w += fg1.y * fg1.y;
        }
    }

    atomicAdd(&s_sum[c4 + 0], sumC.x); atomicAdd(&s_sum[c4 + 1], sumC.y);
    atomicAdd(&s_sum[c4 + 2], sumC.z); atomicAdd(&s_sum[c4 + 3], sumC.w);
    atomicAdd(&s_ssq[c4 + 0], ssqC.x); atomicAdd(&s_ssq[c4 + 1], ssqC.y);
    atomicAdd(&s_ssq[c4 + 2], ssqC.z); atomicAdd(&s_ssq[c4 + 3], ssqC.w);
    atomicAdd(&s_sum[128 + c4 + 0], sumG.x); atomicAdd(&s_sum[128 + c4 + 1], sumG.y);
    atomicAdd(&s_sum[128 + c4 + 2], sumG.z); atomicAdd(&s_sum[128 + c4 + 3], sumG.w);
    atomicAdd(&s_ssq[128 + c4 + 0], ssqG.x); atomicAdd(&s_ssq[128 + c4 + 1], ssqG.y);
    atomicAdd(&s_ssq[128 + c4 + 2], ssqG.z); atomicAdd(&s_ssq[128 + c4 + 3], ssqG.w);
    __syncthreads();
    if (tid < 128) {
        atomicAdd(&g_stats[tid], s_sum[tid]);
        atomicAdd(&g_stats[128 + tid], s_ssq[tid]);
    } else {
        int t = tid - 128;
        atomicAdd(&g_stats[256 + t], s_sum[tid]);
        atomicAdd(&g_stats[384 + t], s_ssq[tid]);
    }
}

// ------------------------------------------------------------------
__global__ void finalize_stats(const float* __restrict__ gamC, const float* __restrict__ betC,
                               const float* __restrict__ gamG, const float* __restrict__ betG,
                               float invT) {
    int c = threadIdx.x;  // 128 threads
    float m = g_stats[c] * invT;
    float v = g_stats[128 + c] * invT - m * m;
    float a = rsqrtf(v + BN_EPS) * gamC[c];
    g_scale[c] = a;
    g_scale[128 + c] = betC[c] - m * a;

    m = g_stats[256 + c] * invT;
    v = g_stats[384 + c] * invT - m * m;
    a = rsqrtf(v + BN_EPS) * gamG[c];
    g_scale[256 + c] = a;
    g_scale[384 + c] = betG[c] - m * a;
}

// ------------------------------------------------------------------
__device__ __forceinline__ float sigf(float x) { return 1.0f / (1.0f + __expf(-x)); }

__global__ void pass_scatter(const int* __restrict__ kx, int T) {
    const int lane = threadIdx.x & 31;
    int warp = (blockIdx.x * blockDim.x + threadIdx.x) >> 5;
    const int nw = (gridDim.x * blockDim.x) >> 5;
    const int c4 = lane * 4;

    const float4 ac = reinterpret_cast<const float4*>(g_scale)[lane];
    const float4 bc = reinterpret_cast<const float4*>(g_scale + 128)[lane];
    const float4 ag = reinterpret_cast<const float4*>(g_scale + 256)[lane];
    const float4 bg = reinterpret_cast<const float4*>(g_scale + 384)[lane];

    for (int t0 = warp * 2; t0 < T; t0 += nw * 2) {
        int t1 = t0 + 1;
        bool h1 = t1 < T;
        int k0 = kx[t0];
        int k1 = h1 ? kx[t1] : k0;

        const __half* A0 = g_A + (size_t)t0 * 256;
        const __half* A1 = g_A + (size_t)t1 * 256;
        float4 c0 = ldh4(A0 + c4), g0 = ldh4(A0 + 128 + c4);
        float4 c1, g1;
        if (h1) { c1 = ldh4(A1 + c4); g1 = ldh4(A1 + 128 + c4); }

        {
            float cnx = c0.x * ac.x + bc.x, cny = c0.y * ac.y + bc.y;
            float cnz = c0.z * ac.z + bc.z, cnw = c0.w * ac.w + bc.w;
            float gnx = g0.x * ag.x + bg.x, gny = g0.y * ag.y + bg.y;
            float gnz = g0.z * ag.z + bg.z, gnw = g0.w * ag.w + bg.w;
            __half2* dst = reinterpret_cast<__half2*>(g_seg + (size_t)k0 * 128 + c4);
            atomicAdd(dst, __floats2half2_rn(cnx * sigf(cnx) * sigf(gnx),
                                             cny * sigf(cny) * sigf(gny)));
            atomicAdd(dst + 1, __floats2half2_rn(cnz * sigf(cnz) * sigf(gnz),
                                                 cnw * sigf(cnw) * sigf(gnw)));
        }
        if (h1) {
            float cnx = c1.x * ac.x + bc.x, cny = c1.y * ac.y + bc.y;
            float cnz = c1.z * ac.z + bc.z, cnw = c1.w * ac.w + bc.w;
            float gnx = g1.x * ag.x + bg.x, gny = g1.y * ag.y + bg.y;
            float gnz = g1.z * ag.z + bg.z, gnw = g1.w * ag.w + bg.w;
            __half2* dst = reinterpret_cast<__half2*>(g_seg + (size_t)k1 * 128 + c4);
            atomicAdd(dst, __floats2half2_rn(cnx * sigf(cnx) * sigf(gnx),
                                             cny * sigf(cny) * sigf(gny)));
            atomicAdd(dst + 1, __floats2half2_rn(cnz * sigf(cnz) * sigf(gnz),
                                                 cnw * sigf(cnw) * sigf(gnw)));
        }
    }
}

// ------------------------------------------------------------------
extern "C" void kernel_launch(void* const* d_in, const int* in_sizes, int n_in,
                              void* d_out, int out_size) {
    const float* vertex = (const float*)d_in[0];
    const float* edge   = (const float*)d_in[1];
    const float* angle  = (const float*)d_in[2];
    const int* kx = (const int*)d_in[4];
    const int* jx = (const int*)d_in[5];
    const int* ix = (const int*)d_in[6];
    const float* w_cs = (const float*)d_in[7];
    const float* w_cd = (const float*)d_in[8];
    const float* w_cb = (const float*)d_in[9];
    const float* w_ca = (const float*)d_in[10];
    const float* w_gs = (const float*)d_in[11];
    const float* w_gd = (const float*)d_in[12];
    const float* w_gb = (const float*)d_in[13];
    const float* w_ga = (const float*)d_in[14];
    const float* bcg = (const float*)d_in[15];
    const float* bcb = (const float*)d_in[16];
    const float* bgg = (const float*)d_in[17];
    const float* bgb = (const float*)d_in[18];
    const float* w_out = (const float*)d_in[19];

    const int N = in_sizes[0] / 128;
    const int E = in_sizes[1] / 128;
    const int T = in_sizes[2] / 64;

    __half *pVsrc, *pVdst, *pEp, *pSeg;
    float *pWv, *pWeb, *pWan;
    cudaGetSymbolAddress((void**)&pVsrc, g_Vsrc);
    cudaGetSymbolAddress((void**)&pVdst, g_Vdst);
    cudaGetSymbolAddress((void**)&pEp, g_Ep);
    cudaGetSymbolAddress((void**)&pSeg, g_seg);
    cudaGetSymbolAddress((void**)&pWv, g_Wv);
    cudaGetSymbolAddress((void**)&pWeb, g_Web);
    cudaGetSymbolAddress((void**)&pWan, g_Wan);

    const size_t smem_gemm = 2 * 128 * 72 * sizeof(__half);           // 36864
    const size_t smem_fuse = (2 * 128 * 72 + 128 * 264) * sizeof(__half);  // 104448
    cudaFuncSetAttribute(mma_gemm<128, float, __half>,
                         cudaFuncAttributeMaxDynamicSharedMemorySize, (int)smem_gemm);
    cudaFuncSetAttribute(mma_gemm<128, __half, float>,
                         cudaFuncAttributeMaxDynamicSharedMemorySize, (int)smem_gemm);
    cudaFuncSetAttribute(mma_gemm_vertex,
                         cudaFuncAttributeMaxDynamicSharedMemorySize, (int)smem_gemm);
    cudaFuncSetAttribute(angle_fuse,
                         cudaFuncAttributeMaxDynamicSharedMemorySize, (int)smem_fuse);

    zero_kernel<<<2048, 256>>>(E);
    pack_weights<<<64, 256>>>(w_cs, w_gs, pWv, 16384);           // rows 0-255
    pack_weights<<<64, 256>>>(w_cd, w_gd, pWv + 32768, 16384);   // rows 256-511
    pack_weights<<<64, 256>>>(w_cb, w_gb, pWeb, 16384);
    pack_weights<<<32, 256>>>(w_ca, w_ga, pWan, 8192);

    const int gN = (N + 127) / 128;
    const int gE = (E + 127) / 128;
    const int gT = (T + 127) / 128;

    // vertex: single launch, 4 output tiles (Vsrc core|gate, Vdst core|gate)
    mma_gemm_vertex<<<dim3(gN, 4), 256, smem_gemm>>>(vertex, pWv, pVsrc, pVdst, N);
    mma_gemm<128, float, __half><<<dim3(gE, 2), 256, smem_gemm>>>(
        edge, pWeb, nullptr, pEp, E, 256);

    // fused: angle GEMM (full N=256) + gather-add + BN stats
    angle_fuse<<<gT, 256, smem_fuse>>>(angle, pWan, kx, jx, ix, T);

    finalize_stats<<<1, 128>>>(bcg, bcb, bgg, bgb, 1.0f / (float)T);

    // activation + segment scatter (fp16x2 atomics), x2 unrolled
    pass_scatter<<<1184, 256>>>(kx, T);

    // new_bond = seg(fp16) @ w_out.T + edge_feat  (fp32 output)
    mma_gemm<128, __half, float><<<dim3(gE, 1), 256, smem_gemm>>>(
        pSeg, w_out, edge, (float*)d_out, E, 128);
}